// round 8
// baseline (speedup 1.0000x reference)
#include <cuda_runtime.h>
#include <cuda_bf16.h>
#include <cstdint>

#define BATCH 64
#define LSEQ  500
#define FEAT  256
#define HEADS 4
#define DK    64
#define BH    (BATCH*HEADS)       // 256
#define MROWS (BATCH*LSEQ)        // 32000
#define LPAD  512
#define AST   72                  // smem row stride (bf16 elems) -> 144B

// ---------------- device scratch ----------------
static __device__ __nv_bfloat16 g_wqsT_hi[FEAT*FEAT], g_wqsT_lo[FEAT*FEAT];
static __device__ __nv_bfloat16 g_wvsT_hi[FEAT*FEAT], g_wvsT_lo[FEAT*FEAT];
static __device__ __nv_bfloat16 g_fcwT_hi[FEAT*FEAT], g_fcwT_lo[FEAT*FEAT];
static __device__ __nv_bfloat16 g_w1t_hi[DK*DK],      g_w1t_lo[DK*DK];
static __device__ __nv_bfloat16 g_w2t_hi[LPAD*DK],    g_w2t_lo[LPAD*DK];
static __device__ float         g_b2p[LPAD];
static __device__ __nv_bfloat16 g_qh_hi[BH*LSEQ*DK + 1024], g_qh_lo[BH*LSEQ*DK + 1024];
static __device__ __nv_bfloat16 g_vT_hi[BH*DK*LPAD],  g_vT_lo[BH*DK*LPAD];   // [bh][d][l] pad 0
static __device__ __nv_bfloat16 g_pre_hi[MROWS*FEAT], g_pre_lo[MROWS*FEAT];

// ---------------- helpers ----------------
__device__ __forceinline__ uint32_t smem_u32(const void* p) {
    uint32_t a;
    asm("{ .reg .u64 t; cvta.to.shared.u64 t, %1; cvt.u32.u64 %0, t; }" : "=r"(a) : "l"(p));
    return a;
}
__device__ __forceinline__ uint32_t pack2(__nv_bfloat16 a, __nv_bfloat16 b) {
    return (uint32_t)__bfloat16_as_ushort(a) | ((uint32_t)__bfloat16_as_ushort(b) << 16);
}
__device__ __forceinline__ void split1(float x, __nv_bfloat16& h, __nv_bfloat16& l) {
    h = __float2bfloat16(x);
    l = __float2bfloat16(x - __bfloat162float(h));
}
__device__ __forceinline__ void split2(float x0, float x1, uint32_t& hi, uint32_t& lo) {
    __nv_bfloat16 h0, l0, h1, l1;
    split1(x0, h0, l0);
    split1(x1, h1, l1);
    hi = pack2(h0, h1);
    lo = pack2(l0, l1);
}

__device__ __forceinline__ void mma_bf16(float acc[4], uint32_t a0, uint32_t a1,
                                         uint32_t a2, uint32_t a3,
                                         uint32_t b0, uint32_t b1) {
    asm volatile(
        "mma.sync.aligned.m16n8k16.row.col.f32.bf16.bf16.f32 "
        "{%0,%1,%2,%3}, {%4,%5,%6,%7}, {%8,%9}, {%0,%1,%2,%3};"
        : "+f"(acc[0]), "+f"(acc[1]), "+f"(acc[2]), "+f"(acc[3])
        : "r"(a0), "r"(a1), "r"(a2), "r"(a3), "r"(b0), "r"(b1));
}

template <int NF>
__device__ __forceinline__ void mma_chunk(float (*acc)[4],
                                          const char* aH, const char* aL,
                                          const char* bH, const char* bL,
                                          int mw, int g, int tg) {
#pragma unroll
    for (int ks = 0; ks < 4; ks++) {
        unsigned a0off = (unsigned)(((mw + g) * AST + ks * 16 + tg * 2) * 2);
        unsigned a1off = a0off + 8 * AST * 2;
        uint32_t ah0 = *(const uint32_t*)(aH + a0off);
        uint32_t ah1 = *(const uint32_t*)(aH + a1off);
        uint32_t ah2 = *(const uint32_t*)(aH + a0off + 16);
        uint32_t ah3 = *(const uint32_t*)(aH + a1off + 16);
        uint32_t al0 = *(const uint32_t*)(aL + a0off);
        uint32_t al1 = *(const uint32_t*)(aL + a1off);
        uint32_t al2 = *(const uint32_t*)(aL + a0off + 16);
        uint32_t al3 = *(const uint32_t*)(aL + a1off + 16);
#pragma unroll
        for (int j = 0; j < NF; j++) {
            unsigned boff = (unsigned)(((j * 8 + g) * AST + ks * 16 + tg * 2) * 2);
            uint32_t bh0 = *(const uint32_t*)(bH + boff);
            uint32_t bh1 = *(const uint32_t*)(bH + boff + 16);
            uint32_t bl0 = *(const uint32_t*)(bL + boff);
            uint32_t bl1 = *(const uint32_t*)(bL + boff + 16);
            mma_bf16(acc[j], ah0, ah1, ah2, ah3, bh0, bh1);
            mma_bf16(acc[j], ah0, ah1, ah2, ah3, bl0, bl1);
            mma_bf16(acc[j], al0, al1, al2, al3, bh0, bh1);
        }
    }
}

__device__ __forceinline__ void cp_tile(char* dst, const char* src, int rows,
                                        int valid, int gstride, int tid, int nt) {
    for (int i = tid; i < rows * 8; i += nt) {
        int r = i >> 3, c = (i & 7) << 4;
        uint4 v = make_uint4(0u, 0u, 0u, 0u);
        if (r < valid) v = *(const uint4*)(src + (size_t)r * gstride + c);
        *(uint4*)(dst + r * (AST * 2) + c) = v;
    }
}

__device__ __forceinline__ void cpa16(uint32_t dst, const void* src) {
    asm volatile("cp.async.ca.shared.global [%0], [%1], 16;" :: "r"(dst), "l"(src));
}
#define CP_COMMIT() asm volatile("cp.async.commit_group;" ::: "memory")
#define CP_WAIT(n)  asm volatile("cp.async.wait_group %0;" :: "n"(n) : "memory")

__device__ __forceinline__ void cp_tile_async(uint32_t dst, const char* src,
                                              int rows8, int gstride, int tid) {
    for (int i = tid; i < rows8; i += 256) {
        int r = i >> 3, c = (i & 7) << 4;
        cpa16(dst + (unsigned)(r * (AST * 2) + c), src + (size_t)r * gstride + c);
    }
}

// ---------------------------------------------------------------------------
__global__ __launch_bounds__(256) void setup_w(const float* __restrict__ w_qs,
                                               const float* __restrict__ w_vs,
                                               const float* __restrict__ fcw,
                                               const float* __restrict__ w1,
                                               const float* __restrict__ w2,
                                               const float* __restrict__ b2) {
    int i0 = blockIdx.x * blockDim.x + threadIdx.x;
    int nt = gridDim.x * blockDim.x;
    for (int t = i0; t < FEAT * FEAT; t += nt) {
        int n = t >> 8, k = t & 255;
        split1(w_qs[k * FEAT + n], g_wqsT_hi[t], g_wqsT_lo[t]);
        split1(w_vs[k * FEAT + n], g_wvsT_hi[t], g_wvsT_lo[t]);
        split1(fcw [k * FEAT + n], g_fcwT_hi[t], g_fcwT_lo[t]);
    }
    for (int t = i0; t < DK * DK; t += nt) {
        int n = t >> 6, k = t & 63;
        split1(w1[k * DK + n], g_w1t_hi[t], g_w1t_lo[t]);
    }
    for (int t = i0; t < LPAD * DK; t += nt) {
        int n = t >> 6, k = t & 63;
        float f = (n < LSEQ) ? w2[k * LSEQ + n] : 0.f;
        split1(f, g_w2t_hi[t], g_w2t_lo[t]);
    }
    for (int t = i0; t < LPAD; t += nt)
        g_b2p[t] = (t < LSEQ) ? b2[t] : -1e30f;
}

// ---------------------------------------------------------------------------
// proj: fp32 X @ W -> qh / vT ; split fused in smem fill
// ---------------------------------------------------------------------------
#define PROJ_SMEM (18432*2 + 9216*2)

__global__ __launch_bounds__(256) void proj_kernel(const float* __restrict__ q,
                                                   const float* __restrict__ v) {
    extern __shared__ char sm[];
    char* sA_hi = sm;
    char* sA_lo = sm + 18432;
    char* sB_hi = sm + 36864;
    char* sB_lo = sm + 46080;

    const int tid = threadIdx.x;
    const int w = tid >> 5, lane = tid & 31, g = lane >> 2, tg = lane & 3;
    const int b = blockIdx.x >> 2, t = blockIdx.x & 3;
    const int h = blockIdx.y;
    const int which = blockIdx.z;
    const int l0 = t * 128;
    const int nrows = min(128, LSEQ - l0);
    const int m0 = b * LSEQ + l0;
    const int n0 = h * 64;
    const int mw = w * 16;

    const float* X = which ? v : q;
    const __nv_bfloat16* Wh = which ? g_wvsT_hi : g_wqsT_hi;
    const __nv_bfloat16* Wl = which ? g_wvsT_lo : g_wqsT_lo;

    float acc[8][4];
#pragma unroll
    for (int j = 0; j < 8; j++)
#pragma unroll
        for (int i = 0; i < 4; i++) acc[j][i] = 0.f;

    for (int kc = 0; kc < 4; kc++) {
        int k0 = kc * 64;
        __syncthreads();
        for (int i = tid; i < 128 * 16; i += 256) {
            int r = i >> 4, c4 = (i & 15) << 2;
            float4 a = make_float4(0.f, 0.f, 0.f, 0.f);
            if (r < nrows) a = *(const float4*)(X + (size_t)(m0 + r) * FEAT + k0 + c4);
            uint32_t h0, L0, h1, L1;
            split2(a.x, a.y, h0, L0);
            split2(a.z, a.w, h1, L1);
            unsigned off = (unsigned)(r * (AST * 2) + c4 * 2);
            *(uint2*)(sA_hi + off) = make_uint2(h0, h1);
            *(uint2*)(sA_lo + off) = make_uint2(L0, L1);
        }
        cp_tile(sB_hi, (const char*)(Wh + (size_t)n0 * FEAT + k0), 64, 64, FEAT * 2, tid, 256);
        cp_tile(sB_lo, (const char*)(Wl + (size_t)n0 * FEAT + k0), 64, 64, FEAT * 2, tid, 256);
        __syncthreads();
        mma_chunk<8>(acc, sA_hi, sA_lo, sB_hi, sB_lo, mw, g, tg);
    }

    const int bh = b * HEADS + h;
#pragma unroll
    for (int rr = 0; rr < 2; rr++) {
        int ml = mw + g + rr * 8;
        if (ml >= nrows) continue;
        int l = l0 + ml;
        if (which == 0) {
            size_t base = ((size_t)bh * LSEQ + l) * DK;
#pragma unroll
            for (int j = 0; j < 8; j++) {
                uint32_t hi, lo;
                split2(acc[j][rr * 2], acc[j][rr * 2 + 1], hi, lo);
                *(uint32_t*)(g_qh_hi + base + j * 8 + tg * 2) = hi;
                *(uint32_t*)(g_qh_lo + base + j * 8 + tg * 2) = lo;
            }
        } else {
#pragma unroll
            for (int j = 0; j < 8; j++) {
#pragma unroll
                for (int cc = 0; cc < 2; cc++) {
                    int d = j * 8 + tg * 2 + cc;
                    __nv_bfloat16 hh, ll;
                    split1(acc[j][rr * 2 + cc], hh, ll);
                    int idx = (bh * DK + d) * LPAD + l;
                    g_vT_hi[idx] = hh;
                    g_vT_lo[idx] = ll;
                }
            }
        }
    }
}

// ---------------------------------------------------------------------------
// synth: software-pipelined (exp(c) | logits(c+1) | out(c)), cp.async rings.
// ---------------------------------------------------------------------------
#define OFF_A   0
#define OFF_H   36864
#define OFF_W1  73728
#define OFF_W   92160
#define OFF_V   147456
#define OFF_B1  202752
#define SYN_SMEM (202752 + 256)

__global__ __launch_bounds__(256) void synth_kernel(const float* __restrict__ b1) {
    extern __shared__ char sm[];
    const uint32_t sb = smem_u32(sm);
    float* b1s = (float*)(sm + OFF_B1);

    const int tid = threadIdx.x;
    const int w = tid >> 5, lane = tid & 31, g = lane >> 2, tg = lane & 3;
    const int bh = blockIdx.y;
    const int r0 = blockIdx.x * 128;
    const int nrows = min(128, LSEQ - r0);
    const int mw = w * 16;

    const size_t qh_base = ((size_t)bh * LSEQ + r0) * DK;
    const size_t vt_base = (size_t)bh * DK * LPAD;

    // init copies: G0 = {qh, w1}; G1 = chunk0; G2 = chunk1
    cp_tile_async(sb + OFF_A,          (const char*)(g_qh_hi + qh_base), 1024, DK * 2, tid);
    cp_tile_async(sb + OFF_A + 18432,  (const char*)(g_qh_lo + qh_base), 1024, DK * 2, tid);
    cp_tile_async(sb + OFF_W1,         (const char*)g_w1t_hi, 512, DK * 2, tid);
    cp_tile_async(sb + OFF_W1 + 9216,  (const char*)g_w1t_lo, 512, DK * 2, tid);
    CP_COMMIT();
#pragma unroll
    for (int c = 0; c < 2; c++) {
        uint32_t wb = sb + OFF_W + c * 18432;
        uint32_t vb = sb + OFF_V + c * 18432;
        cp_tile_async(wb,        (const char*)(g_w2t_hi + c * 64 * DK), 512, DK * 2, tid);
        cp_tile_async(wb + 9216, (const char*)(g_w2t_lo + c * 64 * DK), 512, DK * 2, tid);
        cp_tile_async(vb,        (const char*)(g_vT_hi + vt_base + c * 64), 512, LPAD * 2, tid);
        cp_tile_async(vb + 9216, (const char*)(g_vT_lo + vt_base + c * 64), 512, LPAD * 2, tid);
        CP_COMMIT();
    }
    if (tid < 64) b1s[tid] = b1[tid];
    CP_WAIT(2);           // qh + w1 ready
    __syncthreads();

    // phase 1: hid = relu(qh@w1 + b1) -> sH
    {
        float accl[8][4];
#pragma unroll
        for (int j = 0; j < 8; j++)
#pragma unroll
            for (int i = 0; i < 4; i++) accl[j][i] = 0.f;
        mma_chunk<8>(accl, sm + OFF_A, sm + OFF_A + 18432,
                     sm + OFF_W1, sm + OFF_W1 + 9216, mw, g, tg);
#pragma unroll
        for (int j = 0; j < 8; j++) {
            int col = j * 8 + tg * 2;
            uint32_t hi, lo;
            float x0 = fmaxf(accl[j][0] + b1s[col], 0.f);
            float x1 = fmaxf(accl[j][1] + b1s[col + 1], 0.f);
            split2(x0, x1, hi, lo);
            unsigned off = (unsigned)(((mw + g) * AST + col) * 2);
            *(uint32_t*)(sm + OFF_H + off) = hi;
            *(uint32_t*)(sm + OFF_H + 18432 + off) = lo;
            x0 = fmaxf(accl[j][2] + b1s[col], 0.f);
            x1 = fmaxf(accl[j][3] + b1s[col + 1], 0.f);
            split2(x0, x1, hi, lo);
            off += 8 * AST * 2;
            *(uint32_t*)(sm + OFF_H + off) = hi;
            *(uint32_t*)(sm + OFF_H + 18432 + off) = lo;
        }
        __syncwarp();
    }

    // logits(0) pre-computed
    CP_WAIT(1);           // chunk0 resident
    __syncthreads();

    float accl[2][8][4];
#pragma unroll
    for (int j = 0; j < 8; j++)
#pragma unroll
        for (int i = 0; i < 4; i++) accl[0][j][i] = 0.f;
    mma_chunk<8>(accl[0], sm + OFF_H, sm + OFF_H + 18432,
                 sm + OFF_W, sm + OFF_W + 9216, mw, g, tg);

    float acc_o[8][4];
#pragma unroll
    for (int j = 0; j < 8; j++)
#pragma unroll
        for (int i = 0; i < 4; i++) acc_o[j][i] = 0.f;
    float s0 = 0.f, s1 = 0.f;

    for (int c = 0; c < 8; c++) {
        __syncthreads();    // all warps done reading ring slot (c+2)%3's previous contents
        if (c + 2 < 8) {
            int cn = c + 2, slot = cn % 3;
            uint32_t wb = sb + OFF_W + slot * 18432;
            uint32_t vb = sb + OFF_V + slot * 18432;
            cp_tile_async(wb,        (const char*)(g_w2t_hi + cn * 64 * DK), 512, DK * 2, tid);
            cp_tile_async(wb + 9216, (const char*)(g_w2t_lo + cn * 64 * DK), 512, DK * 2, tid);
            cp_tile_async(vb,        (const char*)(g_vT_hi + vt_base + cn * 64), 512, LPAD * 2, tid);
            cp_tile_async(vb + 9216, (const char*)(g_vT_lo + vt_base + cn * 64), 512, LPAD * 2, tid);
        }
        CP_COMMIT();
        CP_WAIT(1);         // chunks <= c+1 resident
        __syncthreads();

        const int cur = c & 1, nxt = cur ^ 1;

        // exp(c): probs -> sA (warp-private rows)
        const int kc = c * 64;
#pragma unroll
        for (int j = 0; j < 8; j++) {
            int col = kc + j * 8 + tg * 2;
            float bb0 = __ldg(&g_b2p[col]), bb1 = __ldg(&g_b2p[col + 1]);
            float p0 = __expf(fminf(accl[cur][j][0] + bb0, 80.f));
            float p1 = __expf(fminf(accl[cur][j][1] + bb1, 80.f));
            s0 += p0 + p1;
            uint32_t hi, lo;
            split2(p0, p1, hi, lo);
            unsigned off = (unsigned)(((mw + g) * AST + j * 8 + tg * 2) * 2);
            *(uint32_t*)(sm + OFF_A + off) = hi;
            *(uint32_t*)(sm + OFF_A + 18432 + off) = lo;
            p0 = __expf(fminf(accl[cur][j][2] + bb0, 80.f));
            p1 = __expf(fminf(accl[cur][j][3] + bb1, 80.f));
            s1 += p0 + p1;
            split2(p0, p1, hi, lo);
            off += 8 * AST * 2;
            *(uint32_t*)(sm + OFF_A + off) = hi;
            *(uint32_t*)(sm + OFF_A + 18432 + off) = lo;
        }
        __syncwarp();

        // logits(c+1): independent of exp(c)/out(c) -> fills tensor pipe
        if (c < 7) {
            const char* wb = sm + OFF_W + ((c + 1) % 3) * 18432;
#pragma unroll
            for (int j = 0; j < 8; j++)
#pragma unroll
                for (int i = 0; i < 4; i++) accl[nxt][j][i] = 0.f;
            mma_chunk<8>(accl[nxt], sm + OFF_H, sm + OFF_H + 18432, wb, wb + 9216, mw, g, tg);
        }

        // out(c) += P @ vT[c]
        const char* vb = sm + OFF_V + (c % 3) * 18432;
        mma_chunk<8>(acc_o, sm + OFF_A, sm + OFF_A + 18432, vb, vb + 9216, mw, g, tg);
        __syncwarp();       // protect P before next iter's overwrite
    }

    s0 += __shfl_xor_sync(0xffffffffu, s0, 1);
    s0 += __shfl_xor_sync(0xffffffffu, s0, 2);
    s1 += __shfl_xor_sync(0xffffffffu, s1, 1);
    s1 += __shfl_xor_sync(0xffffffffu, s1, 2);
    const float inv0 = 1.f / s0, inv1 = 1.f / s1;
    const int b = bh >> 2, hh = bh & 3;
#pragma unroll
    for (int rr = 0; rr < 2; rr++) {
        int ml = mw + g + rr * 8;
        if (ml >= nrows) continue;
        float invv = rr ? inv1 : inv0;
        size_t base = ((size_t)(b * LSEQ + r0 + ml)) * FEAT + hh * 64;
#pragma unroll
        for (int j = 0; j < 8; j++) {
            uint32_t hi, lo;
            split2(acc_o[j][rr * 2] * invv, acc_o[j][rr * 2 + 1] * invv, hi, lo);
            *(uint32_t*)(g_pre_hi + base + j * 8 + tg * 2) = hi;
            *(uint32_t*)(g_pre_lo + base + j * 8 + tg * 2) = lo;
        }
    }
}

// ---------------------------------------------------------------------------
// fc + residual + LayerNorm. grid 500, block 256, 64 rows/CTA.
// warp = (row-group, N-half): acc 16x4 = 64 regs -> 2 CTAs/SM.
// ---------------------------------------------------------------------------
#define FC_A_HI 0
#define FC_A_LO 9216
#define FC_B_HI 18432
#define FC_B_LO 55296
#define FC_SMEM 92160

__global__ __launch_bounds__(256, 2) void fc_ln_kernel(const float* __restrict__ q,
                                                       const float* __restrict__ lng,
                                                       const float* __restrict__ lnb,
                                                       float* __restrict__ out) {
    extern __shared__ char sm[];
    char* sA_hi = sm + FC_A_HI;
    char* sA_lo = sm + FC_A_LO;
    char* sB_hi = sm + FC_B_HI;
    char* sB_lo = sm + FC_B_LO;
    float* partial = (float*)sm;          // overlay after mma: [64][2][2]

    const int tid = threadIdx.x;
    const int w = tid >> 5, lane = tid & 31, g = lane >> 2, tg = lane & 3;
    const int m0 = blockIdx.x * 64;
    const int rg = w >> 1;                // 0..3 row group
    const int nh = w & 1;                 // N half (128 cols)
    const int mw = rg * 16;

    float acc[16][4];
#pragma unroll
    for (int j = 0; j < 16; j++)
#pragma unroll
        for (int i = 0; i < 4; i++) acc[j][i] = 0.f;

    const char* bh_base = sB_hi + nh * 128 * (AST * 2);
    const char* bl_base = sB_lo + nh * 128 * (AST * 2);

    for (int kc = 0; kc < 4; kc++) {
        int k0 = kc * 64;
        __syncthreads();
        cp_tile(sA_hi, (const char*)(g_pre_hi + (size_t)m0 * FEAT + k0), 64, 64, FEAT * 2, tid, 256);
        cp_tile(sA_lo, (const char*)(g_pre_lo + (size_t)m0 * FEAT + k0), 64, 64, FEAT * 2, tid, 256);
        cp_tile(sB_hi, (const char*)(g_fcwT_hi + k0), 256, 256, FEAT * 2, tid, 256);
        cp_tile(sB_lo, (const char*)(g_fcwT_lo + k0), 256, 256, FEAT * 2, tid, 256);
        __syncthreads();
        mma_chunk<16>(acc, sA_hi, sA_lo, bh_base, bl_base, mw, g, tg);
    }
    __syncthreads();      // mma reads done; smem reusable for partials

    // residual + per-half sums
    float sums[2][2];     // [rr][0]=s, [1]=s2
#pragma unroll
    for (int rr = 0; rr < 2; rr++) {
        int r = mw + g + rr * 8;
        const float* qrow = q + (size_t)(m0 + r) * FEAT + nh * 128;
        float s = 0.f, s2 = 0.f;
#pragma unroll
        for (int j = 0; j < 16; j++) {
            float2 qq = *(const float2*)(qrow + j * 8 + tg * 2);
            float x0 = acc[j][rr * 2]     + qq.x;
            float x1 = acc[j][rr * 2 + 1] + qq.y;
            acc[j][rr * 2] = x0;
            acc[j][rr * 2 + 1] = x1;
            s += x0 + x1;
            s2 += x0 * x0 + x1 * x1;
        }
        s  += __shfl_xor_sync(0xffffffffu, s, 1);
        s  += __shfl_xor_sync(0xffffffffu, s, 2);
        s2 += __shfl_xor_sync(0xffffffffu, s2, 1);
        s2 += __shfl_xor_sync(0xffffffffu, s2, 2);
        sums[rr][0] = s;
        sums[rr][1] = s2;
        if (tg == 0) {
            partial[(r * 2 + nh) * 2 + 0] = s;
            partial[(r * 2 + nh) * 2 + 1] = s2;
        }
    }
    __syncthreads();

#pragma unroll
    for (int rr = 0; rr < 2; rr++) {
        int r = mw + g + rr * 8;
        float s  = sums[rr][0] + partial[(r * 2 + (nh ^ 1)) * 2 + 0];
        float s2 = sums[rr][1] + partial[(r * 2 + (nh ^ 1)) * 2 + 1];
        float mu = s * (1.f / FEAT);
        float rstd = rsqrtf(s2 * (1.f / FEAT) - mu * mu + 1e-6f);
        float* orow = out + (size_t)(m0 + r) * FEAT + nh * 128;
#pragma unroll
        for (int j = 0; j < 16; j++) {
            int col = nh * 128 + j * 8 + tg * 2;
            float g0 = __ldg(&lng[col]), g1 = __ldg(&lng[col + 1]);
            float bb0 = __ldg(&lnb[col]), bb1 = __ldg(&lnb[col + 1]);
            float2 o;
            o.x = (acc[j][rr * 2]     - mu) * rstd * g0 + bb0;
            o.y = (acc[j][rr * 2 + 1] - mu) * rstd * g1 + bb1;
            *(float2*)(orow + col - nh * 128) = o;
        }
    }
}

// ---------------------------------------------------------------------------
extern "C" void kernel_launch(void* const* d_in, const int* in_sizes, int n_in,
                              void* d_out, int out_size)
{
    (void)in_sizes; (void)n_in; (void)out_size;
    const float* q    = (const float*)d_in[0];
    const float* v    = (const float*)d_in[2];
    const float* w_qs = (const float*)d_in[3];
    const float* w_vs = (const float*)d_in[4];
    const float* w1   = (const float*)d_in[5];
    const float* b1   = (const float*)d_in[6];
    const float* w2   = (const float*)d_in[7];
    const float* b2   = (const float*)d_in[8];
    const float* fcw  = (const float*)d_in[9];
    const float* lng  = (const float*)d_in[10];
    const float* lnb  = (const float*)d_in[11];
    float* out = (float*)d_out;

    cudaFuncSetAttribute(proj_kernel,  cudaFuncAttributeMaxDynamicSharedMemorySize, PROJ_SMEM);
    cudaFuncSetAttribute(synth_kernel, cudaFuncAttributeMaxDynamicSharedMemorySize, SYN_SMEM);
    cudaFuncSetAttribute(fc_ln_kernel, cudaFuncAttributeMaxDynamicSharedMemorySize, FC_SMEM);

    setup_w<<<128, 256>>>(w_qs, w_vs, fcw, w1, w2, b2);
    proj_kernel<<<dim3(BATCH * 4, HEADS, 2), 256, PROJ_SMEM>>>(q, v);
    synth_kernel<<<dim3(4, BH), 256, SYN_SMEM>>>(b1);
    fc_ln_kernel<<<500, 256, FC_SMEM>>>(q, lng, lnb, out);
}

// round 9
// speedup vs baseline: 1.0716x; 1.0716x over previous
#include <cuda_runtime.h>
#include <cuda_bf16.h>
#include <cstdint>

#define BATCH 64
#define LSEQ  500
#define FEAT  256
#define HEADS 4
#define DK    64
#define BH    (BATCH*HEADS)       // 256
#define MROWS (BATCH*LSEQ)        // 32000
#define LPAD  512
#define AST   72                  // smem row stride (bf16 elems) -> 144B

// ---------------- device scratch ----------------
static __device__ __nv_bfloat16 g_wqsT_hi[FEAT*FEAT], g_wqsT_lo[FEAT*FEAT];
static __device__ __nv_bfloat16 g_wvsT_hi[FEAT*FEAT], g_wvsT_lo[FEAT*FEAT];
static __device__ __nv_bfloat16 g_fcwT_hi[FEAT*FEAT], g_fcwT_lo[FEAT*FEAT];
static __device__ __nv_bfloat16 g_w1t_hi[DK*DK],      g_w1t_lo[DK*DK];
static __device__ __nv_bfloat16 g_w2t_hi[LPAD*DK],    g_w2t_lo[LPAD*DK];
static __device__ float         g_b2p[LPAD];
static __device__ __nv_bfloat16 g_qh_hi[BH*LSEQ*DK + 1024], g_qh_lo[BH*LSEQ*DK + 1024];
static __device__ __nv_bfloat16 g_vT_hi[BH*DK*LPAD],  g_vT_lo[BH*DK*LPAD];   // [bh][d][l] pad 0
static __device__ __nv_bfloat16 g_pre_hi[MROWS*FEAT], g_pre_lo[MROWS*FEAT];

// ---------------- helpers ----------------
__device__ __forceinline__ uint32_t smem_u32(const void* p) {
    uint32_t a;
    asm("{ .reg .u64 t; cvta.to.shared.u64 t, %1; cvt.u32.u64 %0, t; }" : "=r"(a) : "l"(p));
    return a;
}
__device__ __forceinline__ uint32_t pack2(__nv_bfloat16 a, __nv_bfloat16 b) {
    return (uint32_t)__bfloat16_as_ushort(a) | ((uint32_t)__bfloat16_as_ushort(b) << 16);
}
__device__ __forceinline__ void split1(float x, __nv_bfloat16& h, __nv_bfloat16& l) {
    h = __float2bfloat16(x);
    l = __float2bfloat16(x - __bfloat162float(h));
}
__device__ __forceinline__ void split2(float x0, float x1, uint32_t& hi, uint32_t& lo) {
    __nv_bfloat16 h0, l0, h1, l1;
    split1(x0, h0, l0);
    split1(x1, h1, l1);
    hi = pack2(h0, h1);
    lo = pack2(l0, l1);
}

__device__ __forceinline__ void mma_bf16(float acc[4], uint32_t a0, uint32_t a1,
                                         uint32_t a2, uint32_t a3,
                                         uint32_t b0, uint32_t b1) {
    asm volatile(
        "mma.sync.aligned.m16n8k16.row.col.f32.bf16.bf16.f32 "
        "{%0,%1,%2,%3}, {%4,%5,%6,%7}, {%8,%9}, {%0,%1,%2,%3};"
        : "+f"(acc[0]), "+f"(acc[1]), "+f"(acc[2]), "+f"(acc[3])
        : "r"(a0), "r"(a1), "r"(a2), "r"(a3), "r"(b0), "r"(b1));
}
__device__ __forceinline__ void ldsm4(uint32_t& r0, uint32_t& r1, uint32_t& r2, uint32_t& r3,
                                      uint32_t addr) {
    asm volatile("ldmatrix.sync.aligned.m8n8.x4.shared.b16 {%0,%1,%2,%3}, [%4];"
                 : "=r"(r0), "=r"(r1), "=r"(r2), "=r"(r3) : "r"(addr));
}

// LDSM-based 64-deep K chunk: A [>=mw+16][64], B [NF*8][64], stride AST, hi/lo split.
// A matrices: {m0,k0},{m+8,k0},{m0,k8},{m+8,k8}; B per jp: {n0,k0},{n0,k8},{n+8,k0},{n+8,k8}.
template <int NF>
__device__ __forceinline__ void mma_chunk(float (*acc)[4],
                                          uint32_t aH, uint32_t aL,
                                          uint32_t bH, uint32_t bL,
                                          int mw, int lane) {
    const int r  = lane & 7;
    const int q3 = (lane >> 3) & 1;       // matrix-pair selector low
    const int q4 = (lane >> 4) & 1;       // matrix-pair selector high
    const unsigned aoff = (unsigned)(((mw + q3 * 8 + r) * AST + q4 * 8) * 2);
    const unsigned boff = (unsigned)(((q4 * 8 + r) * AST + q3 * 8) * 2);
#pragma unroll
    for (int ks = 0; ks < 4; ks++) {
        uint32_t ah0, ah1, ah2, ah3, al0, al1, al2, al3;
        ldsm4(ah0, ah1, ah2, ah3, aH + aoff + ks * 32);
        ldsm4(al0, al1, al2, al3, aL + aoff + ks * 32);
#pragma unroll
        for (int jp = 0; jp < NF / 2; jp++) {
            uint32_t bh0, bh1, bh2, bh3, bl0, bl1, bl2, bl3;
            unsigned bo = boff + (unsigned)(jp * 16 * AST * 2) + ks * 32;
            ldsm4(bh0, bh1, bh2, bh3, bH + bo);
            ldsm4(bl0, bl1, bl2, bl3, bL + bo);
            mma_bf16(acc[2 * jp],     ah0, ah1, ah2, ah3, bh0, bh1);
            mma_bf16(acc[2 * jp],     ah0, ah1, ah2, ah3, bl0, bl1);
            mma_bf16(acc[2 * jp],     al0, al1, al2, al3, bh0, bh1);
            mma_bf16(acc[2 * jp + 1], ah0, ah1, ah2, ah3, bh2, bh3);
            mma_bf16(acc[2 * jp + 1], ah0, ah1, ah2, ah3, bl2, bl3);
            mma_bf16(acc[2 * jp + 1], al0, al1, al2, al3, bh2, bh3);
        }
    }
}

__device__ __forceinline__ void cp_tile(char* dst, const char* src, int rows,
                                        int valid, int gstride, int tid, int nt) {
    for (int i = tid; i < rows * 8; i += nt) {
        int r = i >> 3, c = (i & 7) << 4;
        uint4 v = make_uint4(0u, 0u, 0u, 0u);
        if (r < valid) v = *(const uint4*)(src + (size_t)r * gstride + c);
        *(uint4*)(dst + r * (AST * 2) + c) = v;
    }
}

__device__ __forceinline__ void cpa16(uint32_t dst, const void* src) {
    asm volatile("cp.async.ca.shared.global [%0], [%1], 16;" :: "r"(dst), "l"(src));
}
#define CP_COMMIT() asm volatile("cp.async.commit_group;" ::: "memory")
#define CP_WAIT(n)  asm volatile("cp.async.wait_group %0;" :: "n"(n) : "memory")

__device__ __forceinline__ void cp_tile_async(uint32_t dst, const char* src,
                                              int rows8, int gstride, int tid) {
    for (int i = tid; i < rows8; i += 256) {
        int r = i >> 3, c = (i & 7) << 4;
        cpa16(dst + (unsigned)(r * (AST * 2) + c), src + (size_t)r * gstride + c);
    }
}

// ---------------------------------------------------------------------------
__global__ __launch_bounds__(256) void setup_w(const float* __restrict__ w_qs,
                                               const float* __restrict__ w_vs,
                                               const float* __restrict__ fcw,
                                               const float* __restrict__ w1,
                                               const float* __restrict__ w2,
                                               const float* __restrict__ b2) {
    int i0 = blockIdx.x * blockDim.x + threadIdx.x;
    int nt = gridDim.x * blockDim.x;
    for (int t = i0; t < FEAT * FEAT; t += nt) {
        int n = t >> 8, k = t & 255;
        split1(w_qs[k * FEAT + n], g_wqsT_hi[t], g_wqsT_lo[t]);
        split1(w_vs[k * FEAT + n], g_wvsT_hi[t], g_wvsT_lo[t]);
        split1(fcw [k * FEAT + n], g_fcwT_hi[t], g_fcwT_lo[t]);
    }
    for (int t = i0; t < DK * DK; t += nt) {
        int n = t >> 6, k = t & 63;
        split1(w1[k * DK + n], g_w1t_hi[t], g_w1t_lo[t]);
    }
    for (int t = i0; t < LPAD * DK; t += nt) {
        int n = t >> 6, k = t & 63;
        float f = (n < LSEQ) ? w2[k * LSEQ + n] : 0.f;
        split1(f, g_w2t_hi[t], g_w2t_lo[t]);
    }
    for (int t = i0; t < LPAD; t += nt)
        g_b2p[t] = (t < LSEQ) ? b2[t] : -1e30f;
}

// ---------------------------------------------------------------------------
// proj: fp32 X @ W -> qh / vT ; split fused in smem fill
// ---------------------------------------------------------------------------
#define PROJ_SMEM (18432*2 + 9216*2)

__global__ __launch_bounds__(256) void proj_kernel(const float* __restrict__ q,
                                                   const float* __restrict__ v) {
    extern __shared__ char sm[];
    const uint32_t sb = smem_u32(sm);
    char* sA_hi = sm;
    char* sA_lo = sm + 18432;
    char* sB_hi = sm + 36864;
    char* sB_lo = sm + 46080;

    const int tid = threadIdx.x;
    const int w = tid >> 5, lane = tid & 31, g = lane >> 2, tg = lane & 3;
    const int b = blockIdx.x >> 2, t = blockIdx.x & 3;
    const int h = blockIdx.y;
    const int which = blockIdx.z;
    const int l0 = t * 128;
    const int nrows = min(128, LSEQ - l0);
    const int m0 = b * LSEQ + l0;
    const int n0 = h * 64;
    const int mw = w * 16;

    const float* X = which ? v : q;
    const __nv_bfloat16* Wh = which ? g_wvsT_hi : g_wqsT_hi;
    const __nv_bfloat16* Wl = which ? g_wvsT_lo : g_wqsT_lo;

    float acc[8][4];
#pragma unroll
    for (int j = 0; j < 8; j++)
#pragma unroll
        for (int i = 0; i < 4; i++) acc[j][i] = 0.f;

    for (int kc = 0; kc < 4; kc++) {
        int k0 = kc * 64;
        __syncthreads();
        for (int i = tid; i < 128 * 16; i += 256) {
            int r = i >> 4, c4 = (i & 15) << 2;
            float4 a = make_float4(0.f, 0.f, 0.f, 0.f);
            if (r < nrows) a = *(const float4*)(X + (size_t)(m0 + r) * FEAT + k0 + c4);
            uint32_t h0, L0, h1, L1;
            split2(a.x, a.y, h0, L0);
            split2(a.z, a.w, h1, L1);
            unsigned off = (unsigned)(r * (AST * 2) + c4 * 2);
            *(uint2*)(sA_hi + off) = make_uint2(h0, h1);
            *(uint2*)(sA_lo + off) = make_uint2(L0, L1);
        }
        cp_tile(sB_hi, (const char*)(Wh + (size_t)n0 * FEAT + k0), 64, 64, FEAT * 2, tid, 256);
        cp_tile(sB_lo, (const char*)(Wl + (size_t)n0 * FEAT + k0), 64, 64, FEAT * 2, tid, 256);
        __syncthreads();
        mma_chunk<8>(acc, sb, sb + 18432, sb + 36864, sb + 46080, mw, lane);
    }

    const int bh = b * HEADS + h;
#pragma unroll
    for (int rr = 0; rr < 2; rr++) {
        int ml = mw + g + rr * 8;
        if (ml >= nrows) continue;
        int l = l0 + ml;
        if (which == 0) {
            size_t base = ((size_t)bh * LSEQ + l) * DK;
#pragma unroll
            for (int j = 0; j < 8; j++) {
                uint32_t hi, lo;
                split2(acc[j][rr * 2], acc[j][rr * 2 + 1], hi, lo);
                *(uint32_t*)(g_qh_hi + base + j * 8 + tg * 2) = hi;
                *(uint32_t*)(g_qh_lo + base + j * 8 + tg * 2) = lo;
            }
        } else {
#pragma unroll
            for (int j = 0; j < 8; j++) {
#pragma unroll
                for (int cc = 0; cc < 2; cc++) {
                    int d = j * 8 + tg * 2 + cc;
                    __nv_bfloat16 hh, ll;
                    split1(acc[j][rr * 2 + cc], hh, ll);
                    int idx = (bh * DK + d) * LPAD + l;
                    g_vT_hi[idx] = hh;
                    g_vT_lo[idx] = ll;
                }
            }
        }
    }
}

// ---------------------------------------------------------------------------
// synth: 4-deep ring, one barrier/chunk, trailing-out pipeline:
//   iter c: exp(c) | logits(c+1) | out(c)
// smem: A 36864 | H 36864 | W ring 4x18432 | V ring 4x18432 | b1 256
// ---------------------------------------------------------------------------
#define OFF_A   0
#define OFF_H   36864
#define OFF_W   73728
#define OFF_V   147456
#define OFF_B1  221184
#define SYN_SMEM (221184 + 256)

__global__ __launch_bounds__(256) void synth_kernel(const float* __restrict__ b1) {
    extern __shared__ char sm[];
    const uint32_t sb = smem_u32(sm);
    float* b1s = (float*)(sm + OFF_B1);

    const int tid = threadIdx.x;
    const int w = tid >> 5, lane = tid & 31, g = lane >> 2, tg = lane & 3;
    const int bh = blockIdx.y;
    const int r0 = blockIdx.x * 128;
    const int nrows = min(128, LSEQ - r0);
    const int mw = w * 16;

    const size_t qh_base = ((size_t)bh * LSEQ + r0) * DK;
    const size_t vt_base = (size_t)bh * DK * LPAD;
    const uint32_t w1b = sb + OFF_V + 3 * 18432;     // w1 parks in V slot 3

    // G0: qh + w1
    cp_tile_async(sb + OFF_A,         (const char*)(g_qh_hi + qh_base), 1024, DK * 2, tid);
    cp_tile_async(sb + OFF_A + 18432, (const char*)(g_qh_lo + qh_base), 1024, DK * 2, tid);
    cp_tile_async(w1b,        (const char*)g_w1t_hi, 512, DK * 2, tid);
    cp_tile_async(w1b + 9216, (const char*)g_w1t_lo, 512, DK * 2, tid);
    CP_COMMIT();
    // G1..G3: chunks 0..2
#pragma unroll
    for (int c = 0; c < 3; c++) {
        uint32_t wb = sb + OFF_W + c * 18432;
        uint32_t vb = sb + OFF_V + c * 18432;
        cp_tile_async(wb,        (const char*)(g_w2t_hi + c * 64 * DK), 512, DK * 2, tid);
        cp_tile_async(wb + 9216, (const char*)(g_w2t_lo + c * 64 * DK), 512, DK * 2, tid);
        cp_tile_async(vb,        (const char*)(g_vT_hi + vt_base + c * 64), 512, LPAD * 2, tid);
        cp_tile_async(vb + 9216, (const char*)(g_vT_lo + vt_base + c * 64), 512, LPAD * 2, tid);
        CP_COMMIT();
    }
    if (tid < 64) b1s[tid] = b1[tid];
    CP_WAIT(3);              // qh + w1 resident
    __syncthreads();

    // phase 1: hid = relu(qh@w1 + b1) -> sH (warp-private rows)
    {
        float accl[8][4];
#pragma unroll
        for (int j = 0; j < 8; j++)
#pragma unroll
            for (int i = 0; i < 4; i++) accl[j][i] = 0.f;
        mma_chunk<8>(accl, sb + OFF_A, sb + OFF_A + 18432, w1b, w1b + 9216, mw, lane);
#pragma unroll
        for (int j = 0; j < 8; j++) {
            int col = j * 8 + tg * 2;
            uint32_t hi, lo;
            float x0 = fmaxf(accl[j][0] + b1s[col], 0.f);
            float x1 = fmaxf(accl[j][1] + b1s[col + 1], 0.f);
            split2(x0, x1, hi, lo);
            unsigned off = (unsigned)(((mw + g) * AST + col) * 2);
            *(uint32_t*)(sm + OFF_H + off) = hi;
            *(uint32_t*)(sm + OFF_H + 18432 + off) = lo;
            x0 = fmaxf(accl[j][2] + b1s[col], 0.f);
            x1 = fmaxf(accl[j][3] + b1s[col + 1], 0.f);
            split2(x0, x1, hi, lo);
            off += 8 * AST * 2;
            *(uint32_t*)(sm + OFF_H + off) = hi;
            *(uint32_t*)(sm + OFF_H + 18432 + off) = lo;
        }
        __syncwarp();
    }

    CP_WAIT(2);              // chunk 0 resident
    __syncthreads();

    // logits(0)
    float accl[8][4];
#pragma unroll
    for (int j = 0; j < 8; j++)
#pragma unroll
        for (int i = 0; i < 4; i++) accl[j][i] = 0.f;
    mma_chunk<8>(accl, sb + OFF_H, sb + OFF_H + 18432,
                 sb + OFF_W, sb + OFF_W + 9216, mw, lane);

    float acc_o[8][4];
#pragma unroll
    for (int j = 0; j < 8; j++)
#pragma unroll
        for (int i = 0; i < 4; i++) acc_o[j][i] = 0.f;
    float s0 = 0.f, s1 = 0.f;

    for (int c = 0; c < 8; c++) {
        if (c < 7) CP_WAIT(1);   // chunks <= c+1 resident (newest group = chunk c+2)
        __syncthreads();         // visibility + ring-slot (c+3)%4 free (last read iter c-1)

        if (c + 3 < 8) {
            int cn = c + 3, slot = cn & 3;
            uint32_t wb = sb + OFF_W + slot * 18432;
            uint32_t vb = sb + OFF_V + slot * 18432;
            cp_tile_async(wb,        (const char*)(g_w2t_hi + cn * 64 * DK), 512, DK * 2, tid);
            cp_tile_async(wb + 9216, (const char*)(g_w2t_lo + cn * 64 * DK), 512, DK * 2, tid);
            cp_tile_async(vb,        (const char*)(g_vT_hi + vt_base + cn * 64), 512, LPAD * 2, tid);
            cp_tile_async(vb + 9216, (const char*)(g_vT_lo + vt_base + cn * 64), 512, LPAD * 2, tid);
        }
        CP_COMMIT();             // uniform group count (possibly empty)

        // exp(c): probs -> sA (warp-private rows)
        const int kc = c * 64;
#pragma unroll
        for (int j = 0; j < 8; j++) {
            int col = kc + j * 8 + tg * 2;
            float bb0 = __ldg(&g_b2p[col]), bb1 = __ldg(&g_b2p[col + 1]);
            float p0 = __expf(fminf(accl[j][0] + bb0, 80.f));
            float p1 = __expf(fminf(accl[j][1] + bb1, 80.f));
            s0 += p0 + p1;
            uint32_t hi, lo;
            split2(p0, p1, hi, lo);
            unsigned off = (unsigned)(((mw + g) * AST + j * 8 + tg * 2) * 2);
            *(uint32_t*)(sm + OFF_A + off) = hi;
            *(uint32_t*)(sm + OFF_A + 18432 + off) = lo;
            p0 = __expf(fminf(accl[j][2] + bb0, 80.f));
            p1 = __expf(fminf(accl[j][3] + bb1, 80.f));
            s1 += p0 + p1;
            split2(p0, p1, hi, lo);
            off += 8 * AST * 2;
            *(uint32_t*)(sm + OFF_A + off) = hi;
            *(uint32_t*)(sm + OFF_A + 18432 + off) = lo;
        }
        __syncwarp();

        // logits(c+1): independent MMA stream to fill the tensor pipe
        if (c < 7) {
            uint32_t wb = sb + OFF_W + ((c + 1) & 3) * 18432;
#pragma unroll
            for (int j = 0; j < 8; j++)
#pragma unroll
                for (int i = 0; i < 4; i++) accl[j][i] = 0.f;
            mma_chunk<8>(accl, sb + OFF_H, sb + OFF_H + 18432, wb, wb + 9216, mw, lane);
        }

        // out(c) += P @ vT[c]
        uint32_t vb = sb + OFF_V + (c & 3) * 18432;
        mma_chunk<8>(acc_o, sb + OFF_A, sb + OFF_A + 18432, vb, vb + 9216, mw, lane);
        __syncwarp();
    }

    s0 += __shfl_xor_sync(0xffffffffu, s0, 1);
    s0 += __shfl_xor_sync(0xffffffffu, s0, 2);
    s1 += __shfl_xor_sync(0xffffffffu, s1, 1);
    s1 += __shfl_xor_sync(0xffffffffu, s1, 2);
    const float inv0 = 1.f / s0, inv1 = 1.f / s1;
    const int b = bh >> 2, hh = bh & 3;
#pragma unroll
    for (int rr = 0; rr < 2; rr++) {
        int ml = mw + g + rr * 8;
        if (ml >= nrows) continue;
        float invv = rr ? inv1 : inv0;
        size_t base = ((size_t)(b * LSEQ + r0 + ml)) * FEAT + hh * 64;
#pragma unroll
        for (int j = 0; j < 8; j++) {
            uint32_t hi, lo;
            split2(acc_o[j][rr * 2] * invv, acc_o[j][rr * 2 + 1] * invv, hi, lo);
            *(uint32_t*)(g_pre_hi + base + j * 8 + tg * 2) = hi;
            *(uint32_t*)(g_pre_lo + base + j * 8 + tg * 2) = lo;
        }
    }
}

// ---------------------------------------------------------------------------
// fc + residual + LayerNorm. grid 500, block 256, 64 rows/CTA, 2 CTAs/SM.
// ---------------------------------------------------------------------------
#define FC_A_HI 0
#define FC_A_LO 9216
#define FC_B_HI 18432
#define FC_B_LO 55296
#define FC_SMEM 92160

__global__ __launch_bounds__(256, 2) void fc_ln_kernel(const float* __restrict__ q,
                                                       const float* __restrict__ lng,
                                                       const float* __restrict__ lnb,
                                                       float* __restrict__ out) {
    extern __shared__ char sm[];
    const uint32_t sb = smem_u32(sm);
    char* sA_hi = sm + FC_A_HI;
    char* sA_lo = sm + FC_A_LO;
    char* sB_hi = sm + FC_B_HI;
    char* sB_lo = sm + FC_B_LO;
    float* partial = (float*)sm;

    const int tid = threadIdx.x;
    const int w = tid >> 5, lane = tid & 31, g = lane >> 2, tg = lane & 3;
    const int m0 = blockIdx.x * 64;
    const int rg = w >> 1;
    const int nh = w & 1;
    const int mw = rg * 16;

    float acc[16][4];
#pragma unroll
    for (int j = 0; j < 16; j++)
#pragma unroll
        for (int i = 0; i < 4; i++) acc[j][i] = 0.f;

    const uint32_t bh_base = sb + FC_B_HI + nh * 128 * (AST * 2);
    const uint32_t bl_base = sb + FC_B_LO + nh * 128 * (AST * 2);

    for (int kc = 0; kc < 4; kc++) {
        int k0 = kc * 64;
        __syncthreads();
        cp_tile(sA_hi, (const char*)(g_pre_hi + (size_t)m0 * FEAT + k0), 64, 64, FEAT * 2, tid, 256);
        cp_tile(sA_lo, (const char*)(g_pre_lo + (size_t)m0 * FEAT + k0), 64, 64, FEAT * 2, tid, 256);
        cp_tile(sB_hi, (const char*)(g_fcwT_hi + k0), 256, 256, FEAT * 2, tid, 256);
        cp_tile(sB_lo, (const char*)(g_fcwT_lo + k0), 256, 256, FEAT * 2, tid, 256);
        __syncthreads();
        mma_chunk<16>(acc, sb + FC_A_HI, sb + FC_A_LO, bh_base, bl_base, mw, lane);
    }
    __syncthreads();

    float sums[2][2];
#pragma unroll
    for (int rr = 0; rr < 2; rr++) {
        int r = mw + g + rr * 8;
        const float* qrow = q + (size_t)(m0 + r) * FEAT + nh * 128;
        float s = 0.f, s2 = 0.f;
#pragma unroll
        for (int j = 0; j < 16; j++) {
            float2 qq = *(const float2*)(qrow + j * 8 + tg * 2);
            float x0 = acc[j][rr * 2]     + qq.x;
            float x1 = acc[j][rr * 2 + 1] + qq.y;
            acc[j][rr * 2] = x0;
            acc[j][rr * 2 + 1] = x1;
            s += x0 + x1;
            s2 += x0 * x0 + x1 * x1;
        }
        s  += __shfl_xor_sync(0xffffffffu, s, 1);
        s  += __shfl_xor_sync(0xffffffffu, s, 2);
        s2 += __shfl_xor_sync(0xffffffffu, s2, 1);
        s2 += __shfl_xor_sync(0xffffffffu, s2, 2);
        sums[rr][0] = s;
        sums[rr][1] = s2;
        if (tg == 0) {
            partial[(r * 2 + nh) * 2 + 0] = s;
            partial[(r * 2 + nh) * 2 + 1] = s2;
        }
    }
    __syncthreads();

#pragma unroll
    for (int rr = 0; rr < 2; rr++) {
        int r = mw + g + rr * 8;
        float s  = sums[rr][0] + partial[(r * 2 + (nh ^ 1)) * 2 + 0];
        float s2 = sums[rr][1] + partial[(r * 2 + (nh ^ 1)) * 2 + 1];
        float mu = s * (1.f / FEAT);
        float rstd = rsqrtf(s2 * (1.f / FEAT) - mu * mu + 1e-6f);
        float* orow = out + (size_t)(m0 + r) * FEAT + nh * 128;
#pragma unroll
        for (int j = 0; j < 16; j++) {
            int col = nh * 128 + j * 8 + tg * 2;
            float g0 = __ldg(&lng[col]), g1 = __ldg(&lng[col + 1]);
            float bb0 = __ldg(&lnb[col]), bb1 = __ldg(&lnb[col + 1]);
            float2 o;
            o.x = (acc[j][rr * 2]     - mu) * rstd * g0 + bb0;
            o.y = (acc[j][rr * 2 + 1] - mu) * rstd * g1 + bb1;
            *(float2*)(orow + col - nh * 128) = o;
        }
    }
}

// ---------------------------------------------------------------------------
extern "C" void kernel_launch(void* const* d_in, const int* in_sizes, int n_in,
                              void* d_out, int out_size)
{
    (void)in_sizes; (void)n_in; (void)out_size;
    const float* q    = (const float*)d_in[0];
    const float* v    = (const float*)d_in[2];
    const float* w_qs = (const float*)d_in[3];
    const float* w_vs = (const float*)d_in[4];
    const float* w1   = (const float*)d_in[5];
    const float* b1   = (const float*)d_in[6];
    const float* w2   = (const float*)d_in[7];
    const float* b2   = (const float*)d_in[8];
    const float* fcw  = (const float*)d_in[9];
    const float* lng  = (const float*)d_in[10];
    const float* lnb  = (const float*)d_in[11];
    float* out = (float*)d_out;

    cudaFuncSetAttribute(proj_kernel,  cudaFuncAttributeMaxDynamicSharedMemorySize, PROJ_SMEM);
    cudaFuncSetAttribute(synth_kernel, cudaFuncAttributeMaxDynamicSharedMemorySize, SYN_SMEM);
    cudaFuncSetAttribute(fc_ln_kernel, cudaFuncAttributeMaxDynamicSharedMemorySize, FC_SMEM);

    setup_w<<<128, 256>>>(w_qs, w_vs, fcw, w1, w2, b2);
    proj_kernel<<<dim3(BATCH * 4, HEADS, 2), 256, PROJ_SMEM>>>(q, v);
    synth_kernel<<<dim3(4, BH), 256, SYN_SMEM>>>(b1);
    fc_ln_kernel<<<500, 256, FC_SMEM>>>(q, lng, lnb, out);
}

// round 10
// speedup vs baseline: 1.1807x; 1.1018x over previous
#include <cuda_runtime.h>
#include <cuda_bf16.h>
#include <cstdint>

#define BATCH 64
#define LSEQ  500
#define FEAT  256
#define HEADS 4
#define DK    64
#define BH    (BATCH*HEADS)       // 256
#define MROWS (BATCH*LSEQ)        // 32000
#define LPAD  512
#define AST   72                  // smem row stride (bf16 elems) -> 144B

// ---------------- device scratch ----------------
static __device__ __nv_bfloat16 g_wqsT_hi[FEAT*FEAT], g_wqsT_lo[FEAT*FEAT];
static __device__ __nv_bfloat16 g_wvsT_hi[FEAT*FEAT], g_wvsT_lo[FEAT*FEAT];
static __device__ __nv_bfloat16 g_fcwT_hi[FEAT*FEAT], g_fcwT_lo[FEAT*FEAT];
static __device__ __nv_bfloat16 g_w1t_hi[DK*DK],      g_w1t_lo[DK*DK];
static __device__ __nv_bfloat16 g_w2t_hi[LPAD*DK],    g_w2t_lo[LPAD*DK];
static __device__ float         g_b2p[LPAD];
static __device__ __nv_bfloat16 g_qh_hi[BH*LSEQ*DK + 1024], g_qh_lo[BH*LSEQ*DK + 1024];
static __device__ __nv_bfloat16 g_vT_hi[BH*DK*LPAD],  g_vT_lo[BH*DK*LPAD];   // [bh][d][l] pad 0
static __device__ __nv_bfloat16 g_pre_hi[MROWS*FEAT], g_pre_lo[MROWS*FEAT];

// ---------------- helpers ----------------
__device__ __forceinline__ uint32_t smem_u32(const void* p) {
    uint32_t a;
    asm("{ .reg .u64 t; cvta.to.shared.u64 t, %1; cvt.u32.u64 %0, t; }" : "=r"(a) : "l"(p));
    return a;
}
__device__ __forceinline__ uint32_t pack2(__nv_bfloat16 a, __nv_bfloat16 b) {
    return (uint32_t)__bfloat16_as_ushort(a) | ((uint32_t)__bfloat16_as_ushort(b) << 16);
}
__device__ __forceinline__ void split1(float x, __nv_bfloat16& h, __nv_bfloat16& l) {
    h = __float2bfloat16(x);
    l = __float2bfloat16(x - __bfloat162float(h));
}
__device__ __forceinline__ void split2(float x0, float x1, uint32_t& hi, uint32_t& lo) {
    __nv_bfloat16 h0, l0, h1, l1;
    split1(x0, h0, l0);
    split1(x1, h1, l1);
    hi = pack2(h0, h1);
    lo = pack2(l0, l1);
}

__device__ __forceinline__ void mma_bf16(float acc[4], uint32_t a0, uint32_t a1,
                                         uint32_t a2, uint32_t a3,
                                         uint32_t b0, uint32_t b1) {
    asm volatile(
        "mma.sync.aligned.m16n8k16.row.col.f32.bf16.bf16.f32 "
        "{%0,%1,%2,%3}, {%4,%5,%6,%7}, {%8,%9}, {%0,%1,%2,%3};"
        : "+f"(acc[0]), "+f"(acc[1]), "+f"(acc[2]), "+f"(acc[3])
        : "r"(a0), "r"(a1), "r"(a2), "r"(a3), "r"(b0), "r"(b1));
}
__device__ __forceinline__ void ldsm4(uint32_t& r0, uint32_t& r1, uint32_t& r2, uint32_t& r3,
                                      uint32_t addr) {
    asm volatile("ldmatrix.sync.aligned.m8n8.x4.shared.b16 {%0,%1,%2,%3}, [%4];"
                 : "=r"(r0), "=r"(r1), "=r"(r2), "=r"(r3) : "r"(addr));
}

// LDSM-based 64-deep K chunk: A [>=mw+16][64], B [NF*8][64], stride AST, hi/lo split.
template <int NF>
__device__ __forceinline__ void mma_chunk(float (*acc)[4],
                                          uint32_t aH, uint32_t aL,
                                          uint32_t bH, uint32_t bL,
                                          int mw, int lane) {
    const int r  = lane & 7;
    const int q3 = (lane >> 3) & 1;
    const int q4 = (lane >> 4) & 1;
    const unsigned aoff = (unsigned)(((mw + q3 * 8 + r) * AST + q4 * 8) * 2);
    const unsigned boff = (unsigned)(((q4 * 8 + r) * AST + q3 * 8) * 2);
#pragma unroll
    for (int ks = 0; ks < 4; ks++) {
        uint32_t ah0, ah1, ah2, ah3, al0, al1, al2, al3;
        ldsm4(ah0, ah1, ah2, ah3, aH + aoff + ks * 32);
        ldsm4(al0, al1, al2, al3, aL + aoff + ks * 32);
#pragma unroll
        for (int jp = 0; jp < NF / 2; jp++) {
            uint32_t bh0, bh1, bh2, bh3, bl0, bl1, bl2, bl3;
            unsigned bo = boff + (unsigned)(jp * 16 * AST * 2) + ks * 32;
            ldsm4(bh0, bh1, bh2, bh3, bH + bo);
            ldsm4(bl0, bl1, bl2, bl3, bL + bo);
            mma_bf16(acc[2 * jp],     ah0, ah1, ah2, ah3, bh0, bh1);
            mma_bf16(acc[2 * jp],     ah0, ah1, ah2, ah3, bl0, bl1);
            mma_bf16(acc[2 * jp],     al0, al1, al2, al3, bh0, bh1);
            mma_bf16(acc[2 * jp + 1], ah0, ah1, ah2, ah3, bh2, bh3);
            mma_bf16(acc[2 * jp + 1], ah0, ah1, ah2, ah3, bl2, bl3);
            mma_bf16(acc[2 * jp + 1], al0, al1, al2, al3, bh2, bh3);
        }
    }
}

__device__ __forceinline__ void cp_tile(char* dst, const char* src, int rows,
                                        int valid, int gstride, int tid, int nt) {
    for (int i = tid; i < rows * 8; i += nt) {
        int r = i >> 3, c = (i & 7) << 4;
        uint4 v = make_uint4(0u, 0u, 0u, 0u);
        if (r < valid) v = *(const uint4*)(src + (size_t)r * gstride + c);
        *(uint4*)(dst + r * (AST * 2) + c) = v;
    }
}

__device__ __forceinline__ void cpa16(uint32_t dst, const void* src) {
    asm volatile("cp.async.ca.shared.global [%0], [%1], 16;" :: "r"(dst), "l"(src));
}
#define CP_COMMIT() asm volatile("cp.async.commit_group;" ::: "memory")
#define CP_WAIT(n)  asm volatile("cp.async.wait_group %0;" :: "n"(n) : "memory")

__device__ __forceinline__ void cp_tile_async(uint32_t dst, const char* src,
                                              int rows8, int gstride, int tid, int nt) {
    for (int i = tid; i < rows8; i += nt) {
        int r = i >> 3, c = (i & 7) << 4;
        cpa16(dst + (unsigned)(r * (AST * 2) + c), src + (size_t)r * gstride + c);
    }
}

// ---------------------------------------------------------------------------
__global__ __launch_bounds__(256) void setup_w(const float* __restrict__ w_qs,
                                               const float* __restrict__ w_vs,
                                               const float* __restrict__ fcw,
                                               const float* __restrict__ w1,
                                               const float* __restrict__ w2,
                                               const float* __restrict__ b2) {
    int i0 = blockIdx.x * blockDim.x + threadIdx.x;
    int nt = gridDim.x * blockDim.x;
    for (int t = i0; t < FEAT * FEAT; t += nt) {
        int n = t >> 8, k = t & 255;
        split1(w_qs[k * FEAT + n], g_wqsT_hi[t], g_wqsT_lo[t]);
        split1(w_vs[k * FEAT + n], g_wvsT_hi[t], g_wvsT_lo[t]);
        split1(fcw [k * FEAT + n], g_fcwT_hi[t], g_fcwT_lo[t]);
    }
    for (int t = i0; t < DK * DK; t += nt) {
        int n = t >> 6, k = t & 63;
        split1(w1[k * DK + n], g_w1t_hi[t], g_w1t_lo[t]);
    }
    for (int t = i0; t < LPAD * DK; t += nt) {
        int n = t >> 6, k = t & 63;
        float f = (n < LSEQ) ? w2[k * LSEQ + n] : 0.f;
        split1(f, g_w2t_hi[t], g_w2t_lo[t]);
    }
    for (int t = i0; t < LPAD; t += nt)
        g_b2p[t] = (t < LSEQ) ? b2[t] : -1e30f;
}

// ---------------------------------------------------------------------------
// proj: fp32 X @ W -> qh / vT ; split fused in smem fill
// ---------------------------------------------------------------------------
#define PROJ_SMEM (18432*2 + 9216*2)

__global__ __launch_bounds__(256) void proj_kernel(const float* __restrict__ q,
                                                   const float* __restrict__ v) {
    extern __shared__ char sm[];
    const uint32_t sb = smem_u32(sm);
    char* sA_hi = sm;
    char* sA_lo = sm + 18432;
    char* sB_hi = sm + 36864;
    char* sB_lo = sm + 46080;

    const int tid = threadIdx.x;
    const int w = tid >> 5, lane = tid & 31, g = lane >> 2, tg = lane & 3;
    const int b = blockIdx.x >> 2, t = blockIdx.x & 3;
    const int h = blockIdx.y;
    const int which = blockIdx.z;
    const int l0 = t * 128;
    const int nrows = min(128, LSEQ - l0);
    const int m0 = b * LSEQ + l0;
    const int n0 = h * 64;
    const int mw = w * 16;

    const float* X = which ? v : q;
    const __nv_bfloat16* Wh = which ? g_wvsT_hi : g_wqsT_hi;
    const __nv_bfloat16* Wl = which ? g_wvsT_lo : g_wqsT_lo;

    float acc[8][4];
#pragma unroll
    for (int j = 0; j < 8; j++)
#pragma unroll
        for (int i = 0; i < 4; i++) acc[j][i] = 0.f;

    for (int kc = 0; kc < 4; kc++) {
        int k0 = kc * 64;
        __syncthreads();
        for (int i = tid; i < 128 * 16; i += 256) {
            int r = i >> 4, c4 = (i & 15) << 2;
            float4 a = make_float4(0.f, 0.f, 0.f, 0.f);
            if (r < nrows) a = *(const float4*)(X + (size_t)(m0 + r) * FEAT + k0 + c4);
            uint32_t h0, L0, h1, L1;
            split2(a.x, a.y, h0, L0);
            split2(a.z, a.w, h1, L1);
            unsigned off = (unsigned)(r * (AST * 2) + c4 * 2);
            *(uint2*)(sA_hi + off) = make_uint2(h0, h1);
            *(uint2*)(sA_lo + off) = make_uint2(L0, L1);
        }
        cp_tile(sB_hi, (const char*)(Wh + (size_t)n0 * FEAT + k0), 64, 64, FEAT * 2, tid, 256);
        cp_tile(sB_lo, (const char*)(Wl + (size_t)n0 * FEAT + k0), 64, 64, FEAT * 2, tid, 256);
        __syncthreads();
        mma_chunk<8>(acc, sb, sb + 18432, sb + 36864, sb + 46080, mw, lane);
    }

    const int bh = b * HEADS + h;
#pragma unroll
    for (int rr = 0; rr < 2; rr++) {
        int ml = mw + g + rr * 8;
        if (ml >= nrows) continue;
        int l = l0 + ml;
        if (which == 0) {
            size_t base = ((size_t)bh * LSEQ + l) * DK;
#pragma unroll
            for (int j = 0; j < 8; j++) {
                uint32_t hi, lo;
                split2(acc[j][rr * 2], acc[j][rr * 2 + 1], hi, lo);
                *(uint32_t*)(g_qh_hi + base + j * 8 + tg * 2) = hi;
                *(uint32_t*)(g_qh_lo + base + j * 8 + tg * 2) = lo;
            }
        } else {
#pragma unroll
            for (int j = 0; j < 8; j++) {
#pragma unroll
                for (int cc = 0; cc < 2; cc++) {
                    int d = j * 8 + tg * 2 + cc;
                    __nv_bfloat16 hh, ll;
                    split1(acc[j][rr * 2 + cc], hh, ll);
                    int idx = (bh * DK + d) * LPAD + l;
                    g_vT_hi[idx] = hh;
                    g_vT_lo[idx] = ll;
                }
            }
        }
    }
}

// ---------------------------------------------------------------------------
// synth: M-tile 64, 128 threads, depth-2 {W,V} ring -> 110.8KB -> 2 CTAs/SM.
// Per chunk: CP_WAIT(0); sync; prefetch(c+1); logits(c); exp(c); out(c).
// smem: A hi@0 lo@9216 | H hi@18432 lo@27648 | W 2x18432@36864 | V 2x18432@73728 | b1@110592
// ---------------------------------------------------------------------------
#define SY_A   0
#define SY_H   18432
#define SY_W   36864
#define SY_V   73728
#define SY_B1  110592
#define SYN_SMEM (110592 + 256)

__global__ __launch_bounds__(128, 2) void synth_kernel(const float* __restrict__ b1) {
    extern __shared__ char sm[];
    const uint32_t sb = smem_u32(sm);
    float* b1s = (float*)(sm + SY_B1);

    const int tid = threadIdx.x;
    const int w = tid >> 5, lane = tid & 31, g = lane >> 2, tg = lane & 3;
    const int bh = blockIdx.y;
    const int r0 = blockIdx.x * 64;
    const int nrows = min(64, LSEQ - r0);
    const int mw = w * 16;

    const size_t qh_base = ((size_t)bh * LSEQ + r0) * DK;
    const size_t vt_base = (size_t)bh * DK * LPAD;
    const uint32_t w1b = sb + SY_V + 18432;          // w1 parks in V slot 1

    // G0: qh (64 rows, pad overread OK) + w1
    cp_tile_async(sb + SY_A,        (const char*)(g_qh_hi + qh_base), 512, DK * 2, tid, 128);
    cp_tile_async(sb + SY_A + 9216, (const char*)(g_qh_lo + qh_base), 512, DK * 2, tid, 128);
    cp_tile_async(w1b,        (const char*)g_w1t_hi, 512, DK * 2, tid, 128);
    cp_tile_async(w1b + 9216, (const char*)g_w1t_lo, 512, DK * 2, tid, 128);
    CP_COMMIT();
    // G1: chunk 0
    cp_tile_async(sb + SY_W,        (const char*)g_w2t_hi, 512, DK * 2, tid, 128);
    cp_tile_async(sb + SY_W + 9216, (const char*)g_w2t_lo, 512, DK * 2, tid, 128);
    cp_tile_async(sb + SY_V,        (const char*)(g_vT_hi + vt_base), 512, LPAD * 2, tid, 128);
    cp_tile_async(sb + SY_V + 9216, (const char*)(g_vT_lo + vt_base), 512, LPAD * 2, tid, 128);
    CP_COMMIT();
    if (tid < 64) b1s[tid] = b1[tid];
    CP_WAIT(1);              // G0 (qh + w1) resident
    __syncthreads();

    // phase 1: hid = relu(qh@w1 + b1) -> sH (warp-private rows)
    {
        float accl[8][4];
#pragma unroll
        for (int j = 0; j < 8; j++)
#pragma unroll
            for (int i = 0; i < 4; i++) accl[j][i] = 0.f;
        mma_chunk<8>(accl, sb + SY_A, sb + SY_A + 9216, w1b, w1b + 9216, mw, lane);
#pragma unroll
        for (int j = 0; j < 8; j++) {
            int col = j * 8 + tg * 2;
            uint32_t hi, lo;
            float x0 = fmaxf(accl[j][0] + b1s[col], 0.f);
            float x1 = fmaxf(accl[j][1] + b1s[col + 1], 0.f);
            split2(x0, x1, hi, lo);
            unsigned off = (unsigned)(((mw + g) * AST + col) * 2);
            *(uint32_t*)(sm + SY_H + off) = hi;
            *(uint32_t*)(sm + SY_H + 9216 + off) = lo;
            x0 = fmaxf(accl[j][2] + b1s[col], 0.f);
            x1 = fmaxf(accl[j][3] + b1s[col + 1], 0.f);
            split2(x0, x1, hi, lo);
            off += 8 * AST * 2;
            *(uint32_t*)(sm + SY_H + off) = hi;
            *(uint32_t*)(sm + SY_H + 9216 + off) = lo;
        }
        __syncwarp();
    }

    float acc_o[8][4];
#pragma unroll
    for (int j = 0; j < 8; j++)
#pragma unroll
        for (int i = 0; i < 4; i++) acc_o[j][i] = 0.f;
    float s0 = 0.f, s1 = 0.f;

    for (int c = 0; c < 8; c++) {
        CP_WAIT(0);          // chunk c copies (this thread) complete
        __syncthreads();     // chunk c visible to all; slot (c+1)&1 free (phase1/iter c-1 done)

        if (c + 1 < 8) {     // prefetch chunk c+1
            int cn = c + 1, slot = cn & 1;
            uint32_t wb = sb + SY_W + slot * 18432;
            uint32_t vb = sb + SY_V + slot * 18432;
            cp_tile_async(wb,        (const char*)(g_w2t_hi + cn * 64 * DK), 512, DK * 2, tid, 128);
            cp_tile_async(wb + 9216, (const char*)(g_w2t_lo + cn * 64 * DK), 512, DK * 2, tid, 128);
            cp_tile_async(vb,        (const char*)(g_vT_hi + vt_base + cn * 64), 512, LPAD * 2, tid, 128);
            cp_tile_async(vb + 9216, (const char*)(g_vT_lo + vt_base + cn * 64), 512, LPAD * 2, tid, 128);
        }
        CP_COMMIT();

        const uint32_t wb = sb + SY_W + (c & 1) * 18432;
        const uint32_t vb = sb + SY_V + (c & 1) * 18432;

        // logits(c)
        float accl[8][4];
#pragma unroll
        for (int j = 0; j < 8; j++)
#pragma unroll
            for (int i = 0; i < 4; i++) accl[j][i] = 0.f;
        mma_chunk<8>(accl, sb + SY_H, sb + SY_H + 9216, wb, wb + 9216, mw, lane);

        // exp(c): probs -> sA (warp-private rows)
        const int kc = c * 64;
#pragma unroll
        for (int j = 0; j < 8; j++) {
            int col = kc + j * 8 + tg * 2;
            float bb0 = __ldg(&g_b2p[col]), bb1 = __ldg(&g_b2p[col + 1]);
            float p0 = __expf(fminf(accl[j][0] + bb0, 80.f));
            float p1 = __expf(fminf(accl[j][1] + bb1, 80.f));
            s0 += p0 + p1;
            uint32_t hi, lo;
            split2(p0, p1, hi, lo);
            unsigned off = (unsigned)(((mw + g) * AST + j * 8 + tg * 2) * 2);
            *(uint32_t*)(sm + SY_A + off) = hi;
            *(uint32_t*)(sm + SY_A + 9216 + off) = lo;
            p0 = __expf(fminf(accl[j][2] + bb0, 80.f));
            p1 = __expf(fminf(accl[j][3] + bb1, 80.f));
            s1 += p0 + p1;
            split2(p0, p1, hi, lo);
            off += 8 * AST * 2;
            *(uint32_t*)(sm + SY_A + off) = hi;
            *(uint32_t*)(sm + SY_A + 9216 + off) = lo;
        }
        __syncwarp();

        // out(c) += P @ vT[c]
        mma_chunk<8>(acc_o, sb + SY_A, sb + SY_A + 9216, vb, vb + 9216, mw, lane);
        __syncwarp();
    }

    s0 += __shfl_xor_sync(0xffffffffu, s0, 1);
    s0 += __shfl_xor_sync(0xffffffffu, s0, 2);
    s1 += __shfl_xor_sync(0xffffffffu, s1, 1);
    s1 += __shfl_xor_sync(0xffffffffu, s1, 2);
    const float inv0 = 1.f / s0, inv1 = 1.f / s1;
    const int b = bh >> 2, hh = bh & 3;
#pragma unroll
    for (int rr = 0; rr < 2; rr++) {
        int ml = mw + g + rr * 8;
        if (ml >= nrows) continue;
        float invv = rr ? inv1 : inv0;
        size_t base = ((size_t)(b * LSEQ + r0 + ml)) * FEAT + hh * 64;
#pragma unroll
        for (int j = 0; j < 8; j++) {
            uint32_t hi, lo;
            split2(acc_o[j][rr * 2] * invv, acc_o[j][rr * 2 + 1] * invv, hi, lo);
            *(uint32_t*)(g_pre_hi + base + j * 8 + tg * 2) = hi;
            *(uint32_t*)(g_pre_lo + base + j * 8 + tg * 2) = lo;
        }
    }
}

// ---------------------------------------------------------------------------
// fc + residual + LayerNorm. grid 500, block 256, 64 rows/CTA, 2 CTAs/SM.
// ---------------------------------------------------------------------------
#define FC_A_HI 0
#define FC_A_LO 9216
#define FC_B_HI 18432
#define FC_B_LO 55296
#define FC_SMEM 92160

__global__ __launch_bounds__(256, 2) void fc_ln_kernel(const float* __restrict__ q,
                                                       const float* __restrict__ lng,
                                                       const float* __restrict__ lnb,
                                                       float* __restrict__ out) {
    extern __shared__ char sm[];
    const uint32_t sb = smem_u32(sm);
    char* sA_hi = sm + FC_A_HI;
    char* sA_lo = sm + FC_A_LO;
    char* sB_hi = sm + FC_B_HI;
    char* sB_lo = sm + FC_B_LO;
    float* partial = (float*)sm;

    const int tid = threadIdx.x;
    const int w = tid >> 5, lane = tid & 31, g = lane >> 2, tg = lane & 3;
    const int m0 = blockIdx.x * 64;
    const int rg = w >> 1;
    const int nh = w & 1;
    const int mw = rg * 16;

    float acc[16][4];
#pragma unroll
    for (int j = 0; j < 16; j++)
#pragma unroll
        for (int i = 0; i < 4; i++) acc[j][i] = 0.f;

    const uint32_t bh_base = sb + FC_B_HI + nh * 128 * (AST * 2);
    const uint32_t bl_base = sb + FC_B_LO + nh * 128 * (AST * 2);

    for (int kc = 0; kc < 4; kc++) {
        int k0 = kc * 64;
        __syncthreads();
        cp_tile(sA_hi, (const char*)(g_pre_hi + (size_t)m0 * FEAT + k0), 64, 64, FEAT * 2, tid, 256);
        cp_tile(sA_lo, (const char*)(g_pre_lo + (size_t)m0 * FEAT + k0), 64, 64, FEAT * 2, tid, 256);
        cp_tile(sB_hi, (const char*)(g_fcwT_hi + k0), 256, 256, FEAT * 2, tid, 256);
        cp_tile(sB_lo, (const char*)(g_fcwT_lo + k0), 256, 256, FEAT * 2, tid, 256);
        __syncthreads();
        mma_chunk<16>(acc, sb + FC_A_HI, sb + FC_A_LO, bh_base, bl_base, mw, lane);
    }
    __syncthreads();

    float sums[2][2];
#pragma unroll
    for (int rr = 0; rr < 2; rr++) {
        int r = mw + g + rr * 8;
        const float* qrow = q + (size_t)(m0 + r) * FEAT + nh * 128;
        float s = 0.f, s2 = 0.f;
#pragma unroll
        for (int j = 0; j < 16; j++) {
            float2 qq = *(const float2*)(qrow + j * 8 + tg * 2);
            float x0 = acc[j][rr * 2]     + qq.x;
            float x1 = acc[j][rr * 2 + 1] + qq.y;
            acc[j][rr * 2] = x0;
            acc[j][rr * 2 + 1] = x1;
            s += x0 + x1;
            s2 += x0 * x0 + x1 * x1;
        }
        s  += __shfl_xor_sync(0xffffffffu, s, 1);
        s  += __shfl_xor_sync(0xffffffffu, s, 2);
        s2 += __shfl_xor_sync(0xffffffffu, s2, 1);
        s2 += __shfl_xor_sync(0xffffffffu, s2, 2);
        sums[rr][0] = s;
        sums[rr][1] = s2;
        if (tg == 0) {
            partial[(r * 2 + nh) * 2 + 0] = s;
            partial[(r * 2 + nh) * 2 + 1] = s2;
        }
    }
    __syncthreads();

#pragma unroll
    for (int rr = 0; rr < 2; rr++) {
        int r = mw + g + rr * 8;
        float s  = sums[rr][0] + partial[(r * 2 + (nh ^ 1)) * 2 + 0];
        float s2 = sums[rr][1] + partial[(r * 2 + (nh ^ 1)) * 2 + 1];
        float mu = s * (1.f / FEAT);
        float rstd = rsqrtf(s2 * (1.f / FEAT) - mu * mu + 1e-6f);
        float* orow = out + (size_t)(m0 + r) * FEAT + nh * 128;
#pragma unroll
        for (int j = 0; j < 16; j++) {
            int col = nh * 128 + j * 8 + tg * 2;
            float g0 = __ldg(&lng[col]), g1 = __ldg(&lng[col + 1]);
            float bb0 = __ldg(&lnb[col]), bb1 = __ldg(&lnb[col + 1]);
            float2 o;
            o.x = (acc[j][rr * 2]     - mu) * rstd * g0 + bb0;
            o.y = (acc[j][rr * 2 + 1] - mu) * rstd * g1 + bb1;
            *(float2*)(orow + col - nh * 128) = o;
        }
    }
}

// ---------------------------------------------------------------------------
extern "C" void kernel_launch(void* const* d_in, const int* in_sizes, int n_in,
                              void* d_out, int out_size)
{
    (void)in_sizes; (void)n_in; (void)out_size;
    const float* q    = (const float*)d_in[0];
    const float* v    = (const float*)d_in[2];
    const float* w_qs = (const float*)d_in[3];
    const float* w_vs = (const float*)d_in[4];
    const float* w1   = (const float*)d_in[5];
    const float* b1   = (const float*)d_in[6];
    const float* w2   = (const float*)d_in[7];
    const float* b2   = (const float*)d_in[8];
    const float* fcw  = (const float*)d_in[9];
    const float* lng  = (const float*)d_in[10];
    const float* lnb  = (const float*)d_in[11];
    float* out = (float*)d_out;

    cudaFuncSetAttribute(proj_kernel,  cudaFuncAttributeMaxDynamicSharedMemorySize, PROJ_SMEM);
    cudaFuncSetAttribute(synth_kernel, cudaFuncAttributeMaxDynamicSharedMemorySize, SYN_SMEM);
    cudaFuncSetAttribute(fc_ln_kernel, cudaFuncAttributeMaxDynamicSharedMemorySize, FC_SMEM);

    setup_w<<<128, 256>>>(w_qs, w_vs, fcw, w1, w2, b2);
    proj_kernel<<<dim3(BATCH * 4, HEADS, 2), 256, PROJ_SMEM>>>(q, v);
    synth_kernel<<<dim3(8, BH), 128, SYN_SMEM>>>(b1);
    fc_ln_kernel<<<500, 256, FC_SMEM>>>(q, lng, lnb, out);
}

// round 11
// speedup vs baseline: 1.2701x; 1.0758x over previous
#include <cuda_runtime.h>
#include <cuda_bf16.h>
#include <cstdint>

#define BATCH 64
#define LSEQ  500
#define FEAT  256
#define HEADS 4
#define DK    64
#define BH    (BATCH*HEADS)       // 256
#define MROWS (BATCH*LSEQ)        // 32000
#define LPAD  512
#define AST   72                  // smem row stride (bf16 elems) -> 144B

// ---------------- device scratch ----------------
static __device__ __nv_bfloat16 g_wqsT_hi[FEAT*FEAT], g_wqsT_lo[FEAT*FEAT];
static __device__ __nv_bfloat16 g_wvsT_hi[FEAT*FEAT], g_wvsT_lo[FEAT*FEAT];
static __device__ __nv_bfloat16 g_fcwT_hi[FEAT*FEAT], g_fcwT_lo[FEAT*FEAT];
static __device__ __nv_bfloat16 g_w1t_hi[DK*DK],      g_w1t_lo[DK*DK];
static __device__ __nv_bfloat16 g_w2t_hi[LPAD*DK],    g_w2t_lo[LPAD*DK];
static __device__ float         g_b2p[LPAD];
static __device__ __nv_bfloat16 g_qh_hi[BH*LSEQ*DK + 1024], g_qh_lo[BH*LSEQ*DK + 1024];
static __device__ __nv_bfloat16 g_vh_hi[BH*LSEQ*DK + 1024], g_vh_lo[BH*LSEQ*DK + 1024]; // [bh][l][d]
static __device__ __nv_bfloat16 g_pre_hi[MROWS*FEAT], g_pre_lo[MROWS*FEAT];

// ---------------- helpers ----------------
__device__ __forceinline__ uint32_t smem_u32(const void* p) {
    uint32_t a;
    asm("{ .reg .u64 t; cvta.to.shared.u64 t, %1; cvt.u32.u64 %0, t; }" : "=r"(a) : "l"(p));
    return a;
}
__device__ __forceinline__ uint32_t pack2(__nv_bfloat16 a, __nv_bfloat16 b) {
    return (uint32_t)__bfloat16_as_ushort(a) | ((uint32_t)__bfloat16_as_ushort(b) << 16);
}
__device__ __forceinline__ void split1(float x, __nv_bfloat16& h, __nv_bfloat16& l) {
    h = __float2bfloat16(x);
    l = __float2bfloat16(x - __bfloat162float(h));
}
__device__ __forceinline__ void split2(float x0, float x1, uint32_t& hi, uint32_t& lo) {
    __nv_bfloat16 h0, l0, h1, l1;
    split1(x0, h0, l0);
    split1(x1, h1, l1);
    hi = pack2(h0, h1);
    lo = pack2(l0, l1);
}

__device__ __forceinline__ void mma_bf16(float acc[4], uint32_t a0, uint32_t a1,
                                         uint32_t a2, uint32_t a3,
                                         uint32_t b0, uint32_t b1) {
    asm volatile(
        "mma.sync.aligned.m16n8k16.row.col.f32.bf16.bf16.f32 "
        "{%0,%1,%2,%3}, {%4,%5,%6,%7}, {%8,%9}, {%0,%1,%2,%3};"
        : "+f"(acc[0]), "+f"(acc[1]), "+f"(acc[2]), "+f"(acc[3])
        : "r"(a0), "r"(a1), "r"(a2), "r"(a3), "r"(b0), "r"(b1));
}
__device__ __forceinline__ void ldsm4(uint32_t& r0, uint32_t& r1, uint32_t& r2, uint32_t& r3,
                                      uint32_t addr) {
    asm volatile("ldmatrix.sync.aligned.m8n8.x4.shared.b16 {%0,%1,%2,%3}, [%4];"
                 : "=r"(r0), "=r"(r1), "=r"(r2), "=r"(r3) : "r"(addr));
}
__device__ __forceinline__ void ldsm4_t(uint32_t& r0, uint32_t& r1, uint32_t& r2, uint32_t& r3,
                                        uint32_t addr) {
    asm volatile("ldmatrix.sync.aligned.m8n8.x4.trans.shared.b16 {%0,%1,%2,%3}, [%4];"
                 : "=r"(r0), "=r"(r1), "=r"(r2), "=r"(r3) : "r"(addr));
}

// LDSM-based 64-deep K chunk: A [>=mw+16][64], B [NF*8][64], stride AST, hi/lo split.
template <int NF>
__device__ __forceinline__ void mma_chunk(float (*acc)[4],
                                          uint32_t aH, uint32_t aL,
                                          uint32_t bH, uint32_t bL,
                                          int mw, int lane) {
    const int r  = lane & 7;
    const int q3 = (lane >> 3) & 1;
    const int q4 = (lane >> 4) & 1;
    const unsigned aoff = (unsigned)(((mw + q3 * 8 + r) * AST + q4 * 8) * 2);
    const unsigned boff = (unsigned)(((q4 * 8 + r) * AST + q3 * 8) * 2);
#pragma unroll
    for (int ks = 0; ks < 4; ks++) {
        uint32_t ah0, ah1, ah2, ah3, al0, al1, al2, al3;
        ldsm4(ah0, ah1, ah2, ah3, aH + aoff + ks * 32);
        ldsm4(al0, al1, al2, al3, aL + aoff + ks * 32);
#pragma unroll
        for (int jp = 0; jp < NF / 2; jp++) {
            uint32_t bh0, bh1, bh2, bh3, bl0, bl1, bl2, bl3;
            unsigned bo = boff + (unsigned)(jp * 16 * AST * 2) + ks * 32;
            ldsm4(bh0, bh1, bh2, bh3, bH + bo);
            ldsm4(bl0, bl1, bl2, bl3, bL + bo);
            mma_bf16(acc[2 * jp],     ah0, ah1, ah2, ah3, bh0, bh1);
            mma_bf16(acc[2 * jp],     ah0, ah1, ah2, ah3, bl0, bl1);
            mma_bf16(acc[2 * jp],     al0, al1, al2, al3, bh0, bh1);
            mma_bf16(acc[2 * jp + 1], ah0, ah1, ah2, ah3, bh2, bh3);
            mma_bf16(acc[2 * jp + 1], ah0, ah1, ah2, ah3, bl2, bl3);
            mma_bf16(acc[2 * jp + 1], al0, al1, al2, al3, bh2, bh3);
        }
    }
}

__device__ __forceinline__ void cp_tile(char* dst, const char* src, int rows,
                                        int valid, int gstride, int tid, int nt) {
    for (int i = tid; i < rows * 8; i += nt) {
        int r = i >> 3, c = (i & 7) << 4;
        uint4 v = make_uint4(0u, 0u, 0u, 0u);
        if (r < valid) v = *(const uint4*)(src + (size_t)r * gstride + c);
        *(uint4*)(dst + r * (AST * 2) + c) = v;
    }
}

__device__ __forceinline__ void cpa16(uint32_t dst, const void* src) {
    asm volatile("cp.async.ca.shared.global [%0], [%1], 16;" :: "r"(dst), "l"(src));
}
#define CP_COMMIT() asm volatile("cp.async.commit_group;" ::: "memory")
#define CP_WAIT(n)  asm volatile("cp.async.wait_group %0;" :: "n"(n) : "memory")

__device__ __forceinline__ void cp_tile_async(uint32_t dst, const char* src,
                                              int rows8, int gstride, int tid, int nt) {
    for (int i = tid; i < rows8; i += nt) {
        int r = i >> 3, c = (i & 7) << 4;
        cpa16(dst + (unsigned)(r * (AST * 2) + c), src + (size_t)r * gstride + c);
    }
}

// ---------------------------------------------------------------------------
__global__ __launch_bounds__(256) void setup_w(const float* __restrict__ w_qs,
                                               const float* __restrict__ w_vs,
                                               const float* __restrict__ fcw,
                                               const float* __restrict__ w1,
                                               const float* __restrict__ w2,
                                               const float* __restrict__ b2) {
    int i0 = blockIdx.x * blockDim.x + threadIdx.x;
    int nt = gridDim.x * blockDim.x;
    for (int t = i0; t < FEAT * FEAT; t += nt) {
        int n = t >> 8, k = t & 255;
        split1(w_qs[k * FEAT + n], g_wqsT_hi[t], g_wqsT_lo[t]);
        split1(w_vs[k * FEAT + n], g_wvsT_hi[t], g_wvsT_lo[t]);
        split1(fcw [k * FEAT + n], g_fcwT_hi[t], g_fcwT_lo[t]);
    }
    for (int t = i0; t < DK * DK; t += nt) {
        int n = t >> 6, k = t & 63;
        split1(w1[k * DK + n], g_w1t_hi[t], g_w1t_lo[t]);
    }
    for (int t = i0; t < LPAD * DK; t += nt) {
        int n = t >> 6, k = t & 63;
        float f = (n < LSEQ) ? w2[k * LSEQ + n] : 0.f;
        split1(f, g_w2t_hi[t], g_w2t_lo[t]);
    }
    for (int t = i0; t < LPAD; t += nt)
        g_b2p[t] = (t < LSEQ) ? b2[t] : -1e30f;
}

// ---------------------------------------------------------------------------
// proj: fp32 X @ W -> qh / vh, both [bh][l][d]; split fused in smem fill
// ---------------------------------------------------------------------------
#define PROJ_SMEM (18432*2 + 9216*2)

__global__ __launch_bounds__(256) void proj_kernel(const float* __restrict__ q,
                                                   const float* __restrict__ v) {
    extern __shared__ char sm[];
    const uint32_t sb = smem_u32(sm);
    char* sA_hi = sm;
    char* sA_lo = sm + 18432;
    char* sB_hi = sm + 36864;
    char* sB_lo = sm + 46080;

    const int tid = threadIdx.x;
    const int w = tid >> 5, lane = tid & 31, g = lane >> 2, tg = lane & 3;
    const int b = blockIdx.x >> 2, t = blockIdx.x & 3;
    const int h = blockIdx.y;
    const int which = blockIdx.z;
    const int l0 = t * 128;
    const int nrows = min(128, LSEQ - l0);
    const int m0 = b * LSEQ + l0;
    const int n0 = h * 64;
    const int mw = w * 16;

    const float* X = which ? v : q;
    const __nv_bfloat16* Wh = which ? g_wvsT_hi : g_wqsT_hi;
    const __nv_bfloat16* Wl = which ? g_wvsT_lo : g_wqsT_lo;
    __nv_bfloat16* Oh = which ? g_vh_hi : g_qh_hi;
    __nv_bfloat16* Ol = which ? g_vh_lo : g_qh_lo;

    float acc[8][4];
#pragma unroll
    for (int j = 0; j < 8; j++)
#pragma unroll
        for (int i = 0; i < 4; i++) acc[j][i] = 0.f;

    for (int kc = 0; kc < 4; kc++) {
        int k0 = kc * 64;
        __syncthreads();
        for (int i = tid; i < 128 * 16; i += 256) {
            int r = i >> 4, c4 = (i & 15) << 2;
            float4 a = make_float4(0.f, 0.f, 0.f, 0.f);
            if (r < nrows) a = *(const float4*)(X + (size_t)(m0 + r) * FEAT + k0 + c4);
            uint32_t h0, L0, h1, L1;
            split2(a.x, a.y, h0, L0);
            split2(a.z, a.w, h1, L1);
            unsigned off = (unsigned)(r * (AST * 2) + c4 * 2);
            *(uint2*)(sA_hi + off) = make_uint2(h0, h1);
            *(uint2*)(sA_lo + off) = make_uint2(L0, L1);
        }
        cp_tile(sB_hi, (const char*)(Wh + (size_t)n0 * FEAT + k0), 64, 64, FEAT * 2, tid, 256);
        cp_tile(sB_lo, (const char*)(Wl + (size_t)n0 * FEAT + k0), 64, 64, FEAT * 2, tid, 256);
        __syncthreads();
        mma_chunk<8>(acc, sb, sb + 18432, sb + 36864, sb + 46080, mw, lane);
    }

    const int bh = b * HEADS + h;
#pragma unroll
    for (int rr = 0; rr < 2; rr++) {
        int ml = mw + g + rr * 8;
        if (ml >= nrows) continue;
        int l = l0 + ml;
        size_t base = ((size_t)bh * LSEQ + l) * DK;
#pragma unroll
        for (int j = 0; j < 8; j++) {
            uint32_t hi, lo;
            split2(acc[j][rr * 2], acc[j][rr * 2 + 1], hi, lo);
            *(uint32_t*)(Oh + base + j * 8 + tg * 2) = hi;
            *(uint32_t*)(Ol + base + j * 8 + tg * 2) = lo;
        }
    }
}

// ---------------------------------------------------------------------------
// synth: M-tile 64, 128 threads, register-resident hid & P fragments,
// depth-2 {W,V} ring, V in [l][d] via ldmatrix.trans. 2 CTAs/SM.
// smem: Q hi@0 lo@9216 | W 2x18432@18432 | V 2x18432@55296 | b1@92160
// ---------------------------------------------------------------------------
#define SY_Q   0
#define SY_W   18432
#define SY_V   55296
#define SY_B1  92160
#define SYN_SMEM (92160 + 256)

__global__ __launch_bounds__(128, 2) void synth_kernel(const float* __restrict__ b1) {
    extern __shared__ char sm[];
    const uint32_t sb = smem_u32(sm);
    float* b1s = (float*)(sm + SY_B1);

    const int tid = threadIdx.x;
    const int w = tid >> 5, lane = tid & 31, g = lane >> 2, tg = lane & 3;
    const int bh = blockIdx.y;
    const int r0 = blockIdx.x * 64;
    const int nrows = min(64, LSEQ - r0);
    const int mw = w * 16;

    const int r7 = lane & 7;
    const int q3 = (lane >> 3) & 1;
    const int q4 = (lane >> 4) & 1;
    const unsigned bo_n = (unsigned)(((q4 * 8 + r7) * AST + q3 * 8) * 2);  // non-trans [n][k]
    const unsigned bo_t = (unsigned)(((q3 * 8 + r7) * AST + q4 * 8) * 2);  // trans     [k][n]

    const size_t qh_base = ((size_t)bh * LSEQ + r0) * DK;
    const size_t vh_base = (size_t)bh * LSEQ * DK;
    const uint32_t w1b = sb + SY_V + 18432;          // w1 parks in V slot 1

    // G0: qh (64 rows, pad overread OK) + w1
    cp_tile_async(sb + SY_Q,        (const char*)(g_qh_hi + qh_base), 512, DK * 2, tid, 128);
    cp_tile_async(sb + SY_Q + 9216, (const char*)(g_qh_lo + qh_base), 512, DK * 2, tid, 128);
    cp_tile_async(w1b,        (const char*)g_w1t_hi, 512, DK * 2, tid, 128);
    cp_tile_async(w1b + 9216, (const char*)g_w1t_lo, 512, DK * 2, tid, 128);
    CP_COMMIT();
    // G1: chunk 0 (w2 rows 0..63 + vh rows 0..63)
    cp_tile_async(sb + SY_W,        (const char*)g_w2t_hi, 512, DK * 2, tid, 128);
    cp_tile_async(sb + SY_W + 9216, (const char*)g_w2t_lo, 512, DK * 2, tid, 128);
    cp_tile_async(sb + SY_V,        (const char*)(g_vh_hi + vh_base), 512, DK * 2, tid, 128);
    cp_tile_async(sb + SY_V + 9216, (const char*)(g_vh_lo + vh_base), 512, DK * 2, tid, 128);
    CP_COMMIT();
    if (tid < 64) b1s[tid] = b1[tid];
    CP_WAIT(1);              // G0 resident
    __syncthreads();

    // phase 1: hid = relu(qh@w1 + b1) -> register A-fragments hfh/hfl[ks][4]
    uint32_t hfh[4][4], hfl[4][4];
    {
        float accl[8][4];
#pragma unroll
        for (int j = 0; j < 8; j++)
#pragma unroll
            for (int i = 0; i < 4; i++) accl[j][i] = 0.f;
        mma_chunk<8>(accl, sb + SY_Q, sb + SY_Q + 9216, w1b, w1b + 9216, mw, lane);
#pragma unroll
        for (int s = 0; s < 4; s++) {
#pragma unroll
            for (int half = 0; half < 2; half++) {
                int j = 2 * s + half;
                float bb0 = b1s[j * 8 + tg * 2], bb1 = b1s[j * 8 + tg * 2 + 1];
                float x0 = fmaxf(accl[j][0] + bb0, 0.f);
                float x1 = fmaxf(accl[j][1] + bb1, 0.f);
                float x2 = fmaxf(accl[j][2] + bb0, 0.f);
                float x3 = fmaxf(accl[j][3] + bb1, 0.f);
                split2(x0, x1, hfh[s][half * 2],     hfl[s][half * 2]);
                split2(x2, x3, hfh[s][half * 2 + 1], hfl[s][half * 2 + 1]);
            }
        }
    }

    float acc_o[8][4];
#pragma unroll
    for (int j = 0; j < 8; j++)
#pragma unroll
        for (int i = 0; i < 4; i++) acc_o[j][i] = 0.f;
    float s0 = 0.f, s1 = 0.f;

    for (int c = 0; c < 8; c++) {
        CP_WAIT(0);          // chunk c resident
        __syncthreads();     // visible to all; slot (c+1)&1 free (readers of iter c-1 done)

        if (c + 1 < 8) {
            int cn = c + 1, slot = cn & 1;
            uint32_t wb = sb + SY_W + slot * 18432;
            uint32_t vb = sb + SY_V + slot * 18432;
            cp_tile_async(wb,        (const char*)(g_w2t_hi + cn * 64 * DK), 512, DK * 2, tid, 128);
            cp_tile_async(wb + 9216, (const char*)(g_w2t_lo + cn * 64 * DK), 512, DK * 2, tid, 128);
            cp_tile_async(vb,        (const char*)(g_vh_hi + vh_base + (size_t)cn * 64 * DK), 512, DK * 2, tid, 128);
            cp_tile_async(vb + 9216, (const char*)(g_vh_lo + vh_base + (size_t)cn * 64 * DK), 512, DK * 2, tid, 128);
        }
        CP_COMMIT();

        const uint32_t wb = sb + SY_W + (c & 1) * 18432;
        const uint32_t vb = sb + SY_V + (c & 1) * 18432;

        // logits(c) = hid @ w2[c] : A in regs, B non-trans from [n][k]
        float accl[8][4];
#pragma unroll
        for (int j = 0; j < 8; j++)
#pragma unroll
            for (int i = 0; i < 4; i++) accl[j][i] = 0.f;
#pragma unroll
        for (int ks = 0; ks < 4; ks++) {
#pragma unroll
            for (int jp = 0; jp < 4; jp++) {
                uint32_t bh0, bh1, bh2, bh3, bl0, bl1, bl2, bl3;
                unsigned bo = bo_n + (unsigned)(jp * 16 * AST * 2) + ks * 32;
                ldsm4(bh0, bh1, bh2, bh3, wb + bo);
                ldsm4(bl0, bl1, bl2, bl3, wb + 9216 + bo);
                mma_bf16(accl[2 * jp],     hfh[ks][0], hfh[ks][1], hfh[ks][2], hfh[ks][3], bh0, bh1);
                mma_bf16(accl[2 * jp],     hfh[ks][0], hfh[ks][1], hfh[ks][2], hfh[ks][3], bl0, bl1);
                mma_bf16(accl[2 * jp],     hfl[ks][0], hfl[ks][1], hfl[ks][2], hfl[ks][3], bh0, bh1);
                mma_bf16(accl[2 * jp + 1], hfh[ks][0], hfh[ks][1], hfh[ks][2], hfh[ks][3], bh2, bh3);
                mma_bf16(accl[2 * jp + 1], hfh[ks][0], hfh[ks][1], hfh[ks][2], hfh[ks][3], bl2, bl3);
                mma_bf16(accl[2 * jp + 1], hfl[ks][0], hfl[ks][1], hfl[ks][2], hfl[ks][3], bh2, bh3);
            }
        }

        // exp(c): P fragments in registers
        uint32_t pfh[4][4], pfl[4][4];
        const int kc = c * 64;
#pragma unroll
        for (int s = 0; s < 4; s++) {
#pragma unroll
            for (int half = 0; half < 2; half++) {
                int j = 2 * s + half;
                int col = kc + j * 8 + tg * 2;
                float bb0 = __ldg(&g_b2p[col]), bb1 = __ldg(&g_b2p[col + 1]);
                float p0 = __expf(fminf(accl[j][0] + bb0, 80.f));
                float p1 = __expf(fminf(accl[j][1] + bb1, 80.f));
                float p2 = __expf(fminf(accl[j][2] + bb0, 80.f));
                float p3 = __expf(fminf(accl[j][3] + bb1, 80.f));
                s0 += p0 + p1;
                s1 += p2 + p3;
                split2(p0, p1, pfh[s][half * 2],     pfl[s][half * 2]);
                split2(p2, p3, pfh[s][half * 2 + 1], pfl[s][half * 2 + 1]);
            }
        }

        // out(c) += P @ vh[c]^T : A in regs, B trans from [l][d]
#pragma unroll
        for (int ks = 0; ks < 4; ks++) {
#pragma unroll
            for (int jp = 0; jp < 4; jp++) {
                uint32_t bh0, bh1, bh2, bh3, bl0, bl1, bl2, bl3;
                unsigned bo = bo_t + (unsigned)(ks * 16 * AST * 2) + jp * 32;
                ldsm4_t(bh0, bh1, bh2, bh3, vb + bo);
                ldsm4_t(bl0, bl1, bl2, bl3, vb + 9216 + bo);
                mma_bf16(acc_o[2 * jp],     pfh[ks][0], pfh[ks][1], pfh[ks][2], pfh[ks][3], bh0, bh1);
                mma_bf16(acc_o[2 * jp],     pfh[ks][0], pfh[ks][1], pfh[ks][2], pfh[ks][3], bl0, bl1);
                mma_bf16(acc_o[2 * jp],     pfl[ks][0], pfl[ks][1], pfl[ks][2], pfl[ks][3], bh0, bh1);
                mma_bf16(acc_o[2 * jp + 1], pfh[ks][0], pfh[ks][1], pfh[ks][2], pfh[ks][3], bh2, bh3);
                mma_bf16(acc_o[2 * jp + 1], pfh[ks][0], pfh[ks][1], pfh[ks][2], pfh[ks][3], bl2, bl3);
                mma_bf16(acc_o[2 * jp + 1], pfl[ks][0], pfl[ks][1], pfl[ks][2], pfl[ks][3], bh2, bh3);
            }
        }
    }

    s0 += __shfl_xor_sync(0xffffffffu, s0, 1);
    s0 += __shfl_xor_sync(0xffffffffu, s0, 2);
    s1 += __shfl_xor_sync(0xffffffffu, s1, 1);
    s1 += __shfl_xor_sync(0xffffffffu, s1, 2);
    const float inv0 = 1.f / s0, inv1 = 1.f / s1;
    const int b = bh >> 2, hh = bh & 3;
#pragma unroll
    for (int rr = 0; rr < 2; rr++) {
        int ml = mw + g + rr * 8;
        if (ml >= nrows) continue;
        float invv = rr ? inv1 : inv0;
        size_t base = ((size_t)(b * LSEQ + r0 + ml)) * FEAT + hh * 64;
#pragma unroll
        for (int j = 0; j < 8; j++) {
            uint32_t hi, lo;
            split2(acc_o[j][rr * 2] * invv, acc_o[j][rr * 2 + 1] * invv, hi, lo);
            *(uint32_t*)(g_pre_hi + base + j * 8 + tg * 2) = hi;
            *(uint32_t*)(g_pre_lo + base + j * 8 + tg * 2) = lo;
        }
    }
}

// ---------------------------------------------------------------------------
// fc + residual + LayerNorm. grid 500, block 256, 64 rows/CTA, 2 CTAs/SM.
// ---------------------------------------------------------------------------
#define FC_A_HI 0
#define FC_A_LO 9216
#define FC_B_HI 18432
#define FC_B_LO 55296
#define FC_SMEM 92160

__global__ __launch_bounds__(256, 2) void fc_ln_kernel(const float* __restrict__ q,
                                                       const float* __restrict__ lng,
                                                       const float* __restrict__ lnb,
                                                       float* __restrict__ out) {
    extern __shared__ char sm[];
    const uint32_t sb = smem_u32(sm);
    char* sA_hi = sm + FC_A_HI;
    char* sA_lo = sm + FC_A_LO;
    char* sB_hi = sm + FC_B_HI;
    char* sB_lo = sm + FC_B_LO;
    float* partial = (float*)sm;

    const int tid = threadIdx.x;
    const int w = tid >> 5, lane = tid & 31, g = lane >> 2, tg = lane & 3;
    const int m0 = blockIdx.x * 64;
    const int rg = w >> 1;
    const int nh = w & 1;
    const int mw = rg * 16;

    float acc[16][4];
#pragma unroll
    for (int j = 0; j < 16; j++)
#pragma unroll
        for (int i = 0; i < 4; i++) acc[j][i] = 0.f;

    const uint32_t bh_base = sb + FC_B_HI + nh * 128 * (AST * 2);
    const uint32_t bl_base = sb + FC_B_LO + nh * 128 * (AST * 2);

    for (int kc = 0; kc < 4; kc++) {
        int k0 = kc * 64;
        __syncthreads();
        cp_tile(sA_hi, (const char*)(g_pre_hi + (size_t)m0 * FEAT + k0), 64, 64, FEAT * 2, tid, 256);
        cp_tile(sA_lo, (const char*)(g_pre_lo + (size_t)m0 * FEAT + k0), 64, 64, FEAT * 2, tid, 256);
        cp_tile(sB_hi, (const char*)(g_fcwT_hi + k0), 256, 256, FEAT * 2, tid, 256);
        cp_tile(sB_lo, (const char*)(g_fcwT_lo + k0), 256, 256, FEAT * 2, tid, 256);
        __syncthreads();
        mma_chunk<16>(acc, sb + FC_A_HI, sb + FC_A_LO, bh_base, bl_base, mw, lane);
    }
    __syncthreads();

    float sums[2][2];
#pragma unroll
    for (int rr = 0; rr < 2; rr++) {
        int r = mw + g + rr * 8;
        const float* qrow = q + (size_t)(m0 + r) * FEAT + nh * 128;
        float s = 0.f, s2 = 0.f;
#pragma unroll
        for (int j = 0; j < 16; j++) {
            float2 qq = *(const float2*)(qrow + j * 8 + tg * 2);
            float x0 = acc[j][rr * 2]     + qq.x;
            float x1 = acc[j][rr * 2 + 1] + qq.y;
            acc[j][rr * 2] = x0;
            acc[j][rr * 2 + 1] = x1;
            s += x0 + x1;
            s2 += x0 * x0 + x1 * x1;
        }
        s  += __shfl_xor_sync(0xffffffffu, s, 1);
        s  += __shfl_xor_sync(0xffffffffu, s, 2);
        s2 += __shfl_xor_sync(0xffffffffu, s2, 1);
        s2 += __shfl_xor_sync(0xffffffffu, s2, 2);
        sums[rr][0] = s;
        sums[rr][1] = s2;
        if (tg == 0) {
            partial[(r * 2 + nh) * 2 + 0] = s;
            partial[(r * 2 + nh) * 2 + 1] = s2;
        }
    }
    __syncthreads();

#pragma unroll
    for (int rr = 0; rr < 2; rr++) {
        int r = mw + g + rr * 8;
        float s  = sums[rr][0] + partial[(r * 2 + (nh ^ 1)) * 2 + 0];
        float s2 = sums[rr][1] + partial[(r * 2 + (nh ^ 1)) * 2 + 1];
        float mu = s * (1.f / FEAT);
        float rstd = rsqrtf(s2 * (1.f / FEAT) - mu * mu + 1e-6f);
        float* orow = out + (size_t)(m0 + r) * FEAT + nh * 128;
#pragma unroll
        for (int j = 0; j < 16; j++) {
            int col = nh * 128 + j * 8 + tg * 2;
            float g0 = __ldg(&lng[col]), g1 = __ldg(&lng[col + 1]);
            float bb0 = __ldg(&lnb[col]), bb1 = __ldg(&lnb[col + 1]);
            float2 o;
            o.x = (acc[j][rr * 2]     - mu) * rstd * g0 + bb0;
            o.y = (acc[j][rr * 2 + 1] - mu) * rstd * g1 + bb1;
            *(float2*)(orow + col - nh * 128) = o;
        }
    }
}

// ---------------------------------------------------------------------------
extern "C" void kernel_launch(void* const* d_in, const int* in_sizes, int n_in,
                              void* d_out, int out_size)
{
    (void)in_sizes; (void)n_in; (void)out_size;
    const float* q    = (const float*)d_in[0];
    const float* v    = (const float*)d_in[2];
    const float* w_qs = (const float*)d_in[3];
    const float* w_vs = (const float*)d_in[4];
    const float* w1   = (const float*)d_in[5];
    const float* b1   = (const float*)d_in[6];
    const float* w2   = (const float*)d_in[7];
    const float* b2   = (const float*)d_in[8];
    const float* fcw  = (const float*)d_in[9];
    const float* lng  = (const float*)d_in[10];
    const float* lnb  = (const float*)d_in[11];
    float* out = (float*)d_out;

    cudaFuncSetAttribute(proj_kernel,  cudaFuncAttributeMaxDynamicSharedMemorySize, PROJ_SMEM);
    cudaFuncSetAttribute(synth_kernel, cudaFuncAttributeMaxDynamicSharedMemorySize, SYN_SMEM);
    cudaFuncSetAttribute(fc_ln_kernel, cudaFuncAttributeMaxDynamicSharedMemorySize, FC_SMEM);

    setup_w<<<128, 256>>>(w_qs, w_vs, fcw, w1, w2, b2);
    proj_kernel<<<dim3(BATCH * 4, HEADS, 2), 256, PROJ_SMEM>>>(q, v);
    synth_kernel<<<dim3(8, BH), 128, SYN_SMEM>>>(b1);
    fc_ln_kernel<<<500, 256, FC_SMEM>>>(q, lng, lnb, out);
}

// round 12
// speedup vs baseline: 1.3437x; 1.0579x over previous
#include <cuda_runtime.h>
#include <cuda_bf16.h>
#include <cstdint>

#define BATCH 64
#define LSEQ  500
#define FEAT  256
#define HEADS 4
#define DK    64
#define BH    (BATCH*HEADS)       // 256
#define MROWS (BATCH*LSEQ)        // 32000
#define LPAD  512
#define AST   72                  // smem row stride (bf16 elems) -> 144B

// ---------------- device scratch ----------------
static __device__ __nv_bfloat16 g_wqsT_hi[FEAT*FEAT], g_wqsT_lo[FEAT*FEAT];
static __device__ __nv_bfloat16 g_wvsT_hi[FEAT*FEAT], g_wvsT_lo[FEAT*FEAT];
static __device__ __nv_bfloat16 g_fcwT_hi[FEAT*FEAT], g_fcwT_lo[FEAT*FEAT];
static __device__ __nv_bfloat16 g_w1t_hi[DK*DK],      g_w1t_lo[DK*DK];
static __device__ __nv_bfloat16 g_w2t_hi[LPAD*DK],    g_w2t_lo[LPAD*DK];
static __device__ float         g_b2p[LPAD];
static __device__ __nv_bfloat16 g_qh_hi[BH*LSEQ*DK + 1024], g_qh_lo[BH*LSEQ*DK + 1024];
static __device__ __nv_bfloat16 g_vh_hi[BH*LSEQ*DK + 1024], g_vh_lo[BH*LSEQ*DK + 1024]; // [bh][l][d]
static __device__ __nv_bfloat16 g_pre_hi[MROWS*FEAT], g_pre_lo[MROWS*FEAT];

// ---------------- helpers ----------------
__device__ __forceinline__ uint32_t smem_u32(const void* p) {
    uint32_t a;
    asm("{ .reg .u64 t; cvta.to.shared.u64 t, %1; cvt.u32.u64 %0, t; }" : "=r"(a) : "l"(p));
    return a;
}
__device__ __forceinline__ uint32_t pack2(__nv_bfloat16 a, __nv_bfloat16 b) {
    return (uint32_t)__bfloat16_as_ushort(a) | ((uint32_t)__bfloat16_as_ushort(b) << 16);
}
__device__ __forceinline__ void split1(float x, __nv_bfloat16& h, __nv_bfloat16& l) {
    h = __float2bfloat16(x);
    l = __float2bfloat16(x - __bfloat162float(h));
}
__device__ __forceinline__ void split2(float x0, float x1, uint32_t& hi, uint32_t& lo) {
    __nv_bfloat16 h0, l0, h1, l1;
    split1(x0, h0, l0);
    split1(x1, h1, l1);
    hi = pack2(h0, h1);
    lo = pack2(l0, l1);
}

__device__ __forceinline__ void mma_bf16(float acc[4], uint32_t a0, uint32_t a1,
                                         uint32_t a2, uint32_t a3,
                                         uint32_t b0, uint32_t b1) {
    asm volatile(
        "mma.sync.aligned.m16n8k16.row.col.f32.bf16.bf16.f32 "
        "{%0,%1,%2,%3}, {%4,%5,%6,%7}, {%8,%9}, {%0,%1,%2,%3};"
        : "+f"(acc[0]), "+f"(acc[1]), "+f"(acc[2]), "+f"(acc[3])
        : "r"(a0), "r"(a1), "r"(a2), "r"(a3), "r"(b0), "r"(b1));
}
__device__ __forceinline__ void ldsm4(uint32_t& r0, uint32_t& r1, uint32_t& r2, uint32_t& r3,
                                      uint32_t addr) {
    asm volatile("ldmatrix.sync.aligned.m8n8.x4.shared.b16 {%0,%1,%2,%3}, [%4];"
                 : "=r"(r0), "=r"(r1), "=r"(r2), "=r"(r3) : "r"(addr));
}
__device__ __forceinline__ void ldsm4_t(uint32_t& r0, uint32_t& r1, uint32_t& r2, uint32_t& r3,
                                        uint32_t addr) {
    asm volatile("ldmatrix.sync.aligned.m8n8.x4.trans.shared.b16 {%0,%1,%2,%3}, [%4];"
                 : "=r"(r0), "=r"(r1), "=r"(r2), "=r"(r3) : "r"(addr));
}

// LDSM-based 64-deep K chunk: A [>=mw+16][64], B [NF*8][64], stride AST, hi/lo split.
template <int NF>
__device__ __forceinline__ void mma_chunk(float (*acc)[4],
                                          uint32_t aH, uint32_t aL,
                                          uint32_t bH, uint32_t bL,
                                          int mw, int lane) {
    const int r  = lane & 7;
    const int q3 = (lane >> 3) & 1;
    const int q4 = (lane >> 4) & 1;
    const unsigned aoff = (unsigned)(((mw + q3 * 8 + r) * AST + q4 * 8) * 2);
    const unsigned boff = (unsigned)(((q4 * 8 + r) * AST + q3 * 8) * 2);
#pragma unroll
    for (int ks = 0; ks < 4; ks++) {
        uint32_t ah0, ah1, ah2, ah3, al0, al1, al2, al3;
        ldsm4(ah0, ah1, ah2, ah3, aH + aoff + ks * 32);
        ldsm4(al0, al1, al2, al3, aL + aoff + ks * 32);
#pragma unroll
        for (int jp = 0; jp < NF / 2; jp++) {
            uint32_t bh0, bh1, bh2, bh3, bl0, bl1, bl2, bl3;
            unsigned bo = boff + (unsigned)(jp * 16 * AST * 2) + ks * 32;
            ldsm4(bh0, bh1, bh2, bh3, bH + bo);
            ldsm4(bl0, bl1, bl2, bl3, bL + bo);
            mma_bf16(acc[2 * jp],     ah0, ah1, ah2, ah3, bh0, bh1);
            mma_bf16(acc[2 * jp],     ah0, ah1, ah2, ah3, bl0, bl1);
            mma_bf16(acc[2 * jp],     al0, al1, al2, al3, bh0, bh1);
            mma_bf16(acc[2 * jp + 1], ah0, ah1, ah2, ah3, bh2, bh3);
            mma_bf16(acc[2 * jp + 1], ah0, ah1, ah2, ah3, bl2, bl3);
            mma_bf16(acc[2 * jp + 1], al0, al1, al2, al3, bh2, bh3);
        }
    }
}

__device__ __forceinline__ void cp_tile(char* dst, const char* src, int rows,
                                        int valid, int gstride, int tid, int nt) {
    for (int i = tid; i < rows * 8; i += nt) {
        int r = i >> 3, c = (i & 7) << 4;
        uint4 v = make_uint4(0u, 0u, 0u, 0u);
        if (r < valid) v = *(const uint4*)(src + (size_t)r * gstride + c);
        *(uint4*)(dst + r * (AST * 2) + c) = v;
    }
}

__device__ __forceinline__ void cpa16(uint32_t dst, const void* src) {
    asm volatile("cp.async.ca.shared.global [%0], [%1], 16;" :: "r"(dst), "l"(src));
}
#define CP_COMMIT() asm volatile("cp.async.commit_group;" ::: "memory")
#define CP_WAIT(n)  asm volatile("cp.async.wait_group %0;" :: "n"(n) : "memory")

__device__ __forceinline__ void cp_tile_async(uint32_t dst, const char* src,
                                              int rows8, int gstride, int tid, int nt) {
    for (int i = tid; i < rows8; i += nt) {
        int r = i >> 3, c = (i & 7) << 4;
        cpa16(dst + (unsigned)(r * (AST * 2) + c), src + (size_t)r * gstride + c);
    }
}

// ---------------------------------------------------------------------------
__global__ __launch_bounds__(256) void setup_w(const float* __restrict__ w_qs,
                                               const float* __restrict__ w_vs,
                                               const float* __restrict__ fcw,
                                               const float* __restrict__ w1,
                                               const float* __restrict__ w2,
                                               const float* __restrict__ b2) {
    int i0 = blockIdx.x * blockDim.x + threadIdx.x;
    int nt = gridDim.x * blockDim.x;
    for (int t = i0; t < FEAT * FEAT; t += nt) {
        int n = t >> 8, k = t & 255;
        split1(w_qs[k * FEAT + n], g_wqsT_hi[t], g_wqsT_lo[t]);
        split1(w_vs[k * FEAT + n], g_wvsT_hi[t], g_wvsT_lo[t]);
        split1(fcw [k * FEAT + n], g_fcwT_hi[t], g_fcwT_lo[t]);
    }
    for (int t = i0; t < DK * DK; t += nt) {
        int n = t >> 6, k = t & 63;
        split1(w1[k * DK + n], g_w1t_hi[t], g_w1t_lo[t]);
    }
    for (int t = i0; t < LPAD * DK; t += nt) {
        int n = t >> 6, k = t & 63;
        float f = (n < LSEQ) ? w2[k * LSEQ + n] : 0.f;
        split1(f, g_w2t_hi[t], g_w2t_lo[t]);
    }
    for (int t = i0; t < LPAD; t += nt)
        g_b2p[t] = (t < LSEQ) ? b2[t] : -1e30f;
}

// ---------------------------------------------------------------------------
// proj: merged heads. CTA = 64 rows x 256 cols (all 4 heads).
// grid (BATCH*8, 2): x -> (b, 64-row tile), y = which. block 256, 2 CTAs/SM.
// ---------------------------------------------------------------------------
#define PR_A_HI 0
#define PR_A_LO 9216
#define PR_B_HI 18432
#define PR_B_LO 55296
#define PROJ_SMEM 92160

__global__ __launch_bounds__(256, 2) void proj_kernel(const float* __restrict__ q,
                                                      const float* __restrict__ v) {
    extern __shared__ char sm[];
    const uint32_t sb = smem_u32(sm);
    char* sA_hi = sm + PR_A_HI;
    char* sA_lo = sm + PR_A_LO;

    const int tid = threadIdx.x;
    const int w = tid >> 5, lane = tid & 31, g = lane >> 2, tg = lane & 3;
    const int b = blockIdx.x >> 3, t = blockIdx.x & 7;
    const int which = blockIdx.y;
    const int l0 = t * 64;
    const int nrows = min(64, LSEQ - l0);
    const int m0 = b * LSEQ + l0;
    const int rg = w >> 1;            // 4 row groups x 16 rows
    const int nh = w & 1;             // 128-col half
    const int mw = rg * 16;

    const float* X = which ? v : q;
    const __nv_bfloat16* Wh = which ? g_wvsT_hi : g_wqsT_hi;
    const __nv_bfloat16* Wl = which ? g_wvsT_lo : g_wqsT_lo;
    __nv_bfloat16* Oh = which ? g_vh_hi : g_qh_hi;
    __nv_bfloat16* Ol = which ? g_vh_lo : g_qh_lo;

    float acc[16][4];
#pragma unroll
    for (int j = 0; j < 16; j++)
#pragma unroll
        for (int i = 0; i < 4; i++) acc[j][i] = 0.f;

    const uint32_t bh_base = sb + PR_B_HI + nh * 128 * (AST * 2);
    const uint32_t bl_base = sb + PR_B_LO + nh * 128 * (AST * 2);

    for (int kc = 0; kc < 4; kc++) {
        int k0 = kc * 64;
        __syncthreads();
        // A: fp32 load + split (64 rows x 64 cols) — done ONCE for all 4 heads
        for (int i = tid; i < 64 * 16; i += 256) {
            int r = i >> 4, c4 = (i & 15) << 2;
            float4 a = make_float4(0.f, 0.f, 0.f, 0.f);
            if (r < nrows) a = *(const float4*)(X + (size_t)(m0 + r) * FEAT + k0 + c4);
            uint32_t h0, L0, h1, L1;
            split2(a.x, a.y, h0, L0);
            split2(a.z, a.w, h1, L1);
            unsigned off = (unsigned)(r * (AST * 2) + c4 * 2);
            *(uint2*)(sA_hi + off) = make_uint2(h0, h1);
            *(uint2*)(sA_lo + off) = make_uint2(L0, L1);
        }
        // B: full W^T k-chunk (256 rows)
        cp_tile(sm + PR_B_HI, (const char*)(Wh + k0), 256, 256, FEAT * 2, tid, 256);
        cp_tile(sm + PR_B_LO, (const char*)(Wl + k0), 256, 256, FEAT * 2, tid, 256);
        __syncthreads();
        mma_chunk<16>(acc, sb + PR_A_HI, sb + PR_A_LO, bh_base, bl_base, mw, lane);
    }

#pragma unroll
    for (int rr = 0; rr < 2; rr++) {
        int ml = mw + g + rr * 8;
        if (ml >= nrows) continue;
        int l = l0 + ml;
#pragma unroll
        for (int j = 0; j < 16; j++) {
            int head = nh * 2 + (j >> 3);
            int d = (j & 7) * 8 + tg * 2;
            size_t base = ((size_t)(b * HEADS + head) * LSEQ + l) * DK + d;
            uint32_t hi, lo;
            split2(acc[j][rr * 2], acc[j][rr * 2 + 1], hi, lo);
            *(uint32_t*)(Oh + base) = hi;
            *(uint32_t*)(Ol + base) = lo;
        }
    }
}

// ---------------------------------------------------------------------------
// synth: M-tile 64, 128 threads, no Q smem (direct LDG fragments),
// depth-2 {W,V} ring -> 74KB -> 3 CTAs/SM.
// smem: W 2x18432@0 | V 2x18432@36864 | b1@73728
// ---------------------------------------------------------------------------
#define SY_W   0
#define SY_V   36864
#define SY_B1  73728
#define SYN_SMEM (73728 + 256)

__global__ __launch_bounds__(128, 3) void synth_kernel(const float* __restrict__ b1) {
    extern __shared__ char sm[];
    const uint32_t sb = smem_u32(sm);
    float* b1s = (float*)(sm + SY_B1);

    const int tid = threadIdx.x;
    const int w = tid >> 5, lane = tid & 31, g = lane >> 2, tg = lane & 3;
    const int bh = blockIdx.y;
    const int r0 = blockIdx.x * 64;
    const int nrows = min(64, LSEQ - r0);
    const int mw = w * 16;

    const int r7 = lane & 7;
    const int q3 = (lane >> 3) & 1;
    const int q4 = (lane >> 4) & 1;
    const unsigned bo_n = (unsigned)(((q4 * 8 + r7) * AST + q3 * 8) * 2);  // non-trans [n][k]
    const unsigned bo_t = (unsigned)(((q3 * 8 + r7) * AST + q4 * 8) * 2);  // trans     [k][n]

    const size_t vh_base = (size_t)bh * LSEQ * DK;
    const uint32_t w1b = sb + SY_V + 18432;          // w1 parks in V slot 1

    // G0: w1
    cp_tile_async(w1b,        (const char*)g_w1t_hi, 512, DK * 2, tid, 128);
    cp_tile_async(w1b + 9216, (const char*)g_w1t_lo, 512, DK * 2, tid, 128);
    CP_COMMIT();
    // G1: chunk 0 (w2 rows 0..63 + vh rows 0..63)
    cp_tile_async(sb + SY_W,        (const char*)g_w2t_hi, 512, DK * 2, tid, 128);
    cp_tile_async(sb + SY_W + 9216, (const char*)g_w2t_lo, 512, DK * 2, tid, 128);
    cp_tile_async(sb + SY_V,        (const char*)(g_vh_hi + vh_base), 512, DK * 2, tid, 128);
    cp_tile_async(sb + SY_V + 9216, (const char*)(g_vh_lo + vh_base), 512, DK * 2, tid, 128);
    CP_COMMIT();
    if (tid < 64) b1s[tid] = b1[tid];

    // qh A-fragments direct from gmem (canonical m16n8k16 A layout; warp-private rows)
    uint32_t qfh[4][4], qfl[4][4];
    {
        const size_t row0 = (size_t)bh * LSEQ + r0 + mw + g;
        const __nv_bfloat16* p0h = g_qh_hi + row0 * DK;
        const __nv_bfloat16* p1h = p0h + 8 * DK;
        const __nv_bfloat16* p0l = g_qh_lo + row0 * DK;
        const __nv_bfloat16* p1l = p0l + 8 * DK;
#pragma unroll
        for (int ks = 0; ks < 4; ks++) {
            int col = ks * 16 + tg * 2;
            qfh[ks][0] = *(const uint32_t*)(p0h + col);
            qfh[ks][1] = *(const uint32_t*)(p1h + col);
            qfh[ks][2] = *(const uint32_t*)(p0h + col + 8);
            qfh[ks][3] = *(const uint32_t*)(p1h + col + 8);
            qfl[ks][0] = *(const uint32_t*)(p0l + col);
            qfl[ks][1] = *(const uint32_t*)(p1l + col);
            qfl[ks][2] = *(const uint32_t*)(p0l + col + 8);
            qfl[ks][3] = *(const uint32_t*)(p1l + col + 8);
        }
    }

    CP_WAIT(1);              // G0 (w1) resident
    __syncthreads();

    // phase 1: hid = relu(qh@w1 + b1) -> register A-fragments hfh/hfl
    uint32_t hfh[4][4], hfl[4][4];
    {
        float accl[8][4];
#pragma unroll
        for (int j = 0; j < 8; j++)
#pragma unroll
            for (int i = 0; i < 4; i++) accl[j][i] = 0.f;
#pragma unroll
        for (int ks = 0; ks < 4; ks++) {
#pragma unroll
            for (int jp = 0; jp < 4; jp++) {
                uint32_t bh0, bh1, bh2, bh3, bl0, bl1, bl2, bl3;
                unsigned bo = bo_n + (unsigned)(jp * 16 * AST * 2) + ks * 32;
                ldsm4(bh0, bh1, bh2, bh3, w1b + bo);
                ldsm4(bl0, bl1, bl2, bl3, w1b + 9216 + bo);
                mma_bf16(accl[2 * jp],     qfh[ks][0], qfh[ks][1], qfh[ks][2], qfh[ks][3], bh0, bh1);
                mma_bf16(accl[2 * jp],     qfh[ks][0], qfh[ks][1], qfh[ks][2], qfh[ks][3], bl0, bl1);
                mma_bf16(accl[2 * jp],     qfl[ks][0], qfl[ks][1], qfl[ks][2], qfl[ks][3], bh0, bh1);
                mma_bf16(accl[2 * jp + 1], qfh[ks][0], qfh[ks][1], qfh[ks][2], qfh[ks][3], bh2, bh3);
                mma_bf16(accl[2 * jp + 1], qfh[ks][0], qfh[ks][1], qfh[ks][2], qfh[ks][3], bl2, bl3);
                mma_bf16(accl[2 * jp + 1], qfl[ks][0], qfl[ks][1], qfl[ks][2], qfl[ks][3], bh2, bh3);
            }
        }
#pragma unroll
        for (int s = 0; s < 4; s++) {
#pragma unroll
            for (int half = 0; half < 2; half++) {
                int j = 2 * s + half;
                float bb0 = b1s[j * 8 + tg * 2], bb1 = b1s[j * 8 + tg * 2 + 1];
                float x0 = fmaxf(accl[j][0] + bb0, 0.f);
                float x1 = fmaxf(accl[j][1] + bb1, 0.f);
                float x2 = fmaxf(accl[j][2] + bb0, 0.f);
                float x3 = fmaxf(accl[j][3] + bb1, 0.f);
                split2(x0, x1, hfh[s][half * 2],     hfl[s][half * 2]);
                split2(x2, x3, hfh[s][half * 2 + 1], hfl[s][half * 2 + 1]);
            }
        }
    }

    float acc_o[8][4];
#pragma unroll
    for (int j = 0; j < 8; j++)
#pragma unroll
        for (int i = 0; i < 4; i++) acc_o[j][i] = 0.f;
    float s0 = 0.f, s1 = 0.f;

    for (int c = 0; c < 8; c++) {
        CP_WAIT(0);          // chunk c resident
        __syncthreads();     // visible to all; slot (c+1)&1 free

        if (c + 1 < 8) {
            int cn = c + 1, slot = cn & 1;
            uint32_t wb = sb + SY_W + slot * 18432;
            uint32_t vb = sb + SY_V + slot * 18432;
            cp_tile_async(wb,        (const char*)(g_w2t_hi + cn * 64 * DK), 512, DK * 2, tid, 128);
            cp_tile_async(wb + 9216, (const char*)(g_w2t_lo + cn * 64 * DK), 512, DK * 2, tid, 128);
            cp_tile_async(vb,        (const char*)(g_vh_hi + vh_base + (size_t)cn * 64 * DK), 512, DK * 2, tid, 128);
            cp_tile_async(vb + 9216, (const char*)(g_vh_lo + vh_base + (size_t)cn * 64 * DK), 512, DK * 2, tid, 128);
        }
        CP_COMMIT();

        const uint32_t wb = sb + SY_W + (c & 1) * 18432;
        const uint32_t vb = sb + SY_V + (c & 1) * 18432;

        // logits(c) = hid @ w2[c]
        float accl[8][4];
#pragma unroll
        for (int j = 0; j < 8; j++)
#pragma unroll
            for (int i = 0; i < 4; i++) accl[j][i] = 0.f;
#pragma unroll
        for (int ks = 0; ks < 4; ks++) {
#pragma unroll
            for (int jp = 0; jp < 4; jp++) {
                uint32_t bh0, bh1, bh2, bh3, bl0, bl1, bl2, bl3;
                unsigned bo = bo_n + (unsigned)(jp * 16 * AST * 2) + ks * 32;
                ldsm4(bh0, bh1, bh2, bh3, wb + bo);
                ldsm4(bl0, bl1, bl2, bl3, wb + 9216 + bo);
                mma_bf16(accl[2 * jp],     hfh[ks][0], hfh[ks][1], hfh[ks][2], hfh[ks][3], bh0, bh1);
                mma_bf16(accl[2 * jp],     hfh[ks][0], hfh[ks][1], hfh[ks][2], hfh[ks][3], bl0, bl1);
                mma_bf16(accl[2 * jp],     hfl[ks][0], hfl[ks][1], hfl[ks][2], hfl[ks][3], bh0, bh1);
                mma_bf16(accl[2 * jp + 1], hfh[ks][0], hfh[ks][1], hfh[ks][2], hfh[ks][3], bh2, bh3);
                mma_bf16(accl[2 * jp + 1], hfh[ks][0], hfh[ks][1], hfh[ks][2], hfh[ks][3], bl2, bl3);
                mma_bf16(accl[2 * jp + 1], hfl[ks][0], hfl[ks][1], hfl[ks][2], hfl[ks][3], bh2, bh3);
            }
        }

        // exp(c): P fragments in registers
        uint32_t pfh[4][4], pfl[4][4];
        const int kc = c * 64;
#pragma unroll
        for (int s = 0; s < 4; s++) {
#pragma unroll
            for (int half = 0; half < 2; half++) {
                int j = 2 * s + half;
                int col = kc + j * 8 + tg * 2;
                float bb0 = __ldg(&g_b2p[col]), bb1 = __ldg(&g_b2p[col + 1]);
                float p0 = __expf(fminf(accl[j][0] + bb0, 80.f));
                float p1 = __expf(fminf(accl[j][1] + bb1, 80.f));
                float p2 = __expf(fminf(accl[j][2] + bb0, 80.f));
                float p3 = __expf(fminf(accl[j][3] + bb1, 80.f));
                s0 += p0 + p1;
                s1 += p2 + p3;
                split2(p0, p1, pfh[s][half * 2],     pfl[s][half * 2]);
                split2(p2, p3, pfh[s][half * 2 + 1], pfl[s][half * 2 + 1]);
            }
        }

        // out(c) += P @ vh[c]^T
#pragma unroll
        for (int ks = 0; ks < 4; ks++) {
#pragma unroll
            for (int jp = 0; jp < 4; jp++) {
                uint32_t bh0, bh1, bh2, bh3, bl0, bl1, bl2, bl3;
                unsigned bo = bo_t + (unsigned)(ks * 16 * AST * 2) + jp * 32;
                ldsm4_t(bh0, bh1, bh2, bh3, vb + bo);
                ldsm4_t(bl0, bl1, bl2, bl3, vb + 9216 + bo);
                mma_bf16(acc_o[2 * jp],     pfh[ks][0], pfh[ks][1], pfh[ks][2], pfh[ks][3], bh0, bh1);
                mma_bf16(acc_o[2 * jp],     pfh[ks][0], pfh[ks][1], pfh[ks][2], pfh[ks][3], bl0, bl1);
                mma_bf16(acc_o[2 * jp],     pfl[ks][0], pfl[ks][1], pfl[ks][2], pfl[ks][3], bh0, bh1);
                mma_bf16(acc_o[2 * jp + 1], pfh[ks][0], pfh[ks][1], pfh[ks][2], pfh[ks][3], bh2, bh3);
                mma_bf16(acc_o[2 * jp + 1], pfh[ks][0], pfh[ks][1], pfh[ks][2], pfh[ks][3], bl2, bl3);
                mma_bf16(acc_o[2 * jp + 1], pfl[ks][0], pfl[ks][1], pfl[ks][2], pfl[ks][3], bh2, bh3);
            }
        }
    }

    s0 += __shfl_xor_sync(0xffffffffu, s0, 1);
    s0 += __shfl_xor_sync(0xffffffffu, s0, 2);
    s1 += __shfl_xor_sync(0xffffffffu, s1, 1);
    s1 += __shfl_xor_sync(0xffffffffu, s1, 2);
    const float inv0 = 1.f / s0, inv1 = 1.f / s1;
    const int b = bh >> 2, hh = bh & 3;
#pragma unroll
    for (int rr = 0; rr < 2; rr++) {
        int ml = mw + g + rr * 8;
        if (ml >= nrows) continue;
        float invv = rr ? inv1 : inv0;
        size_t base = ((size_t)(b * LSEQ + r0 + ml)) * FEAT + hh * 64;
#pragma unroll
        for (int j = 0; j < 8; j++) {
            uint32_t hi, lo;
            split2(acc_o[j][rr * 2] * invv, acc_o[j][rr * 2 + 1] * invv, hi, lo);
            *(uint32_t*)(g_pre_hi + base + j * 8 + tg * 2) = hi;
            *(uint32_t*)(g_pre_lo + base + j * 8 + tg * 2) = lo;
        }
    }
}

// ---------------------------------------------------------------------------
// fc + residual + LayerNorm. grid 500, block 256, 64 rows/CTA, 2 CTAs/SM.
// ---------------------------------------------------------------------------
#define FC_A_HI 0
#define FC_A_LO 9216
#define FC_B_HI 18432
#define FC_B_LO 55296
#define FC_SMEM 92160

__global__ __launch_bounds__(256, 2) void fc_ln_kernel(const float* __restrict__ q,
                                                       const float* __restrict__ lng,
                                                       const float* __restrict__ lnb,
                                                       float* __restrict__ out) {
    extern __shared__ char sm[];
    const uint32_t sb = smem_u32(sm);
    char* sA_hi = sm + FC_A_HI;
    char* sA_lo = sm + FC_A_LO;
    char* sB_hi = sm + FC_B_HI;
    char* sB_lo = sm + FC_B_LO;
    float* partial = (float*)sm;

    const int tid = threadIdx.x;
    const int w = tid >> 5, lane = tid & 31, g = lane >> 2, tg = lane & 3;
    const int m0 = blockIdx.x * 64;
    const int rg = w >> 1;
    const int nh = w & 1;
    const int mw = rg * 16;

    float acc[16][4];
#pragma unroll
    for (int j = 0; j < 16; j++)
#pragma unroll
        for (int i = 0; i < 4; i++) acc[j][i] = 0.f;

    const uint32_t bh_base = sb + FC_B_HI + nh * 128 * (AST * 2);
    const uint32_t bl_base = sb + FC_B_LO + nh * 128 * (AST * 2);

    for (int kc = 0; kc < 4; kc++) {
        int k0 = kc * 64;
        __syncthreads();
        cp_tile(sA_hi, (const char*)(g_pre_hi + (size_t)m0 * FEAT + k0), 64, 64, FEAT * 2, tid, 256);
        cp_tile(sA_lo, (const char*)(g_pre_lo + (size_t)m0 * FEAT + k0), 64, 64, FEAT * 2, tid, 256);
        cp_tile(sB_hi, (const char*)(g_fcwT_hi + k0), 256, 256, FEAT * 2, tid, 256);
        cp_tile(sB_lo, (const char*)(g_fcwT_lo + k0), 256, 256, FEAT * 2, tid, 256);
        __syncthreads();
        mma_chunk<16>(acc, sb + FC_A_HI, sb + FC_A_LO, bh_base, bl_base, mw, lane);
    }
    __syncthreads();

    float sums[2][2];
#pragma unroll
    for (int rr = 0; rr < 2; rr++) {
        int r = mw + g + rr * 8;
        const float* qrow = q + (size_t)(m0 + r) * FEAT + nh * 128;
        float s = 0.f, s2 = 0.f;
#pragma unroll
        for (int j = 0; j < 16; j++) {
            float2 qq = *(const float2*)(qrow + j * 8 + tg * 2);
            float x0 = acc[j][rr * 2]     + qq.x;
            float x1 = acc[j][rr * 2 + 1] + qq.y;
            acc[j][rr * 2] = x0;
            acc[j][rr * 2 + 1] = x1;
            s += x0 + x1;
            s2 += x0 * x0 + x1 * x1;
        }
        s  += __shfl_xor_sync(0xffffffffu, s, 1);
        s  += __shfl_xor_sync(0xffffffffu, s, 2);
        s2 += __shfl_xor_sync(0xffffffffu, s2, 1);
        s2 += __shfl_xor_sync(0xffffffffu, s2, 2);
        sums[rr][0] = s;
        sums[rr][1] = s2;
        if (tg == 0) {
            partial[(r * 2 + nh) * 2 + 0] = s;
            partial[(r * 2 + nh) * 2 + 1] = s2;
        }
    }
    __syncthreads();

#pragma unroll
    for (int rr = 0; rr < 2; rr++) {
        int r = mw + g + rr * 8;
        float s  = sums[rr][0] + partial[(r * 2 + (nh ^ 1)) * 2 + 0];
        float s2 = sums[rr][1] + partial[(r * 2 + (nh ^ 1)) * 2 + 1];
        float mu = s * (1.f / FEAT);
        float rstd = rsqrtf(s2 * (1.f / FEAT) - mu * mu + 1e-6f);
        float* orow = out + (size_t)(m0 + r) * FEAT + nh * 128;
#pragma unroll
        for (int j = 0; j < 16; j++) {
            int col = nh * 128 + j * 8 + tg * 2;
            float g0 = __ldg(&lng[col]), g1 = __ldg(&lng[col + 1]);
            float bb0 = __ldg(&lnb[col]), bb1 = __ldg(&lnb[col + 1]);
            float2 o;
            o.x = (acc[j][rr * 2]     - mu) * rstd * g0 + bb0;
            o.y = (acc[j][rr * 2 + 1] - mu) * rstd * g1 + bb1;
            *(float2*)(orow + col - nh * 128) = o;
        }
    }
}

// ---------------------------------------------------------------------------
extern "C" void kernel_launch(void* const* d_in, const int* in_sizes, int n_in,
                              void* d_out, int out_size)
{
    (void)in_sizes; (void)n_in; (void)out_size;
    const float* q    = (const float*)d_in[0];
    const float* v    = (const float*)d_in[2];
    const float* w_qs = (const float*)d_in[3];
    const float* w_vs = (const float*)d_in[4];
    const float* w1   = (const float*)d_in[5];
    const float* b1   = (const float*)d_in[6];
    const float* w2   = (const float*)d_in[7];
    const float* b2   = (const float*)d_in[8];
    const float* fcw  = (const float*)d_in[9];
    const float* lng  = (const float*)d_in[10];
    const float* lnb  = (const float*)d_in[11];
    float* out = (float*)d_out;

    cudaFuncSetAttribute(proj_kernel,  cudaFuncAttributeMaxDynamicSharedMemorySize, PROJ_SMEM);
    cudaFuncSetAttribute(synth_kernel, cudaFuncAttributeMaxDynamicSharedMemorySize, SYN_SMEM);
    cudaFuncSetAttribute(fc_ln_kernel, cudaFuncAttributeMaxDynamicSharedMemorySize, FC_SMEM);

    setup_w<<<128, 256>>>(w_qs, w_vs, fcw, w1, w2, b2);
    proj_kernel<<<dim3(BATCH * 8, 2), 256, PROJ_SMEM>>>(q, v);
    synth_kernel<<<dim3(8, BH), 128, SYN_SMEM>>>(b1);
    fc_ln_kernel<<<500, 256, FC_SMEM>>>(q, lng, lnb, out);
}